// round 10
// baseline (speedup 1.0000x reference)
#include <cuda_runtime.h>
#include <cuda_fp16.h>
#include <mma.h>
#include <math.h>
#include <stdint.h>

using namespace nvcuda;

// ---------------------------------------------------------------------------
// MemoryGatedAttention  (B=4, T=S=2048, D=1024, H=16, DH=64, M=64)
// Round 10 (re-bench of R9 after infra failure): fp16 wmma with
//   (a) 64x64 warp-tile GEMM (2x mma per fragment load),
//   (b) flash with warp-local softmax -> 1 block barrier per tile.
// ---------------------------------------------------------------------------

namespace cfg {
constexpr int B  = 4;
constexpr int T  = 2048;
constexpr int S  = 2048;
constexpr int D  = 1024;
constexpr int H  = 16;
constexpr int DH = 64;
constexpr int M  = 64;
constexpr int BT = B * T;
// flash smem (bytes)
constexpr int LDH = 72;
constexpr int LDS = 68;
constexpr int FL_KS_H   = 2 * 64 * LDH;
constexpr int FL_VS_H   = 2 * 64 * LDH;
constexpr int FL_PS_H   = 128 * LDH;
constexpr int FL_SS_F   = 128 * LDS;
constexpr int FL_BYTES  = (FL_KS_H + FL_VS_H + FL_PS_H) * 2
                        + FL_SS_F * 4 + (3 * 128 + 256) * 4;   // ~92.7KB
// gemm dynamic smem (bytes): As 2*128*40h + Bs 2*32*264h + idx 256f
constexpr int GA_STRIDE = 40;     // halves
constexpr int GB_STRIDE = 264;    // halves
constexpr int G_AS_OFF  = 0;                          // halves offsets
constexpr int G_AS_SZ   = 128 * GA_STRIDE;            // 5120 halves
constexpr int G_BS_OFF  = 2 * G_AS_SZ;                // 10240
constexpr int G_BS_SZ   = 32 * GB_STRIDE;             // 8448 halves
constexpr int G_IDX_OFF = G_BS_OFF + 2 * G_BS_SZ;     // halves offset (even)
constexpr int G_SMEM    = (G_IDX_OFF + 512) * 2 + 1024;  // ~56.3KB
}

// ----------------------------- scratch --------------------------------------
__device__ __half g_qh[cfg::BT * cfg::D];
__device__ __half g_kh[cfg::BT * cfg::D];
__device__ __half g_vh[cfg::BT * cfg::D];
__device__ __half g_Wqh[cfg::D * cfg::D];
__device__ __half g_Wkh[cfg::D * cfg::D];
__device__ __half g_Wvh[cfg::D * cfg::D];
__device__ __half g_Woh[cfg::D * cfg::D];
__device__ __half g_Qh[cfg::BT * cfg::D];
__device__ __half g_Kh[cfg::BT * cfg::D];
__device__ __half g_Vh[cfg::BT * cfg::D];
__device__ __half g_Oh[cfg::BT * cfg::D];
__device__ float  g_memin[cfg::B * 2 * cfg::D];
__device__ float  g_gatevals[cfg::B * cfg::D];
__device__ float  g_scale_val;

// ----------------------------- cp.async helpers ------------------------------
__device__ __forceinline__ void cp_async16(void* smem_dst, const void* gmem_src) {
    unsigned sa = (unsigned)__cvta_generic_to_shared(smem_dst);
    asm volatile("cp.async.cg.shared.global [%0], [%1], 16;\n" :: "r"(sa), "l"(gmem_src));
}
__device__ __forceinline__ void cp_commit() {
    asm volatile("cp.async.commit_group;\n");
}
template <int N>
__device__ __forceinline__ void cp_wait() {
    asm volatile("cp.async.wait_group %0;\n" :: "n"(N));
}

// ----------------------------- fragment types --------------------------------
using HFragA  = wmma::fragment<wmma::matrix_a, 16, 16, 16, __half, wmma::row_major>;
using HFragBr = wmma::fragment<wmma::matrix_b, 16, 16, 16, __half, wmma::row_major>;
using HFragBc = wmma::fragment<wmma::matrix_b, 16, 16, 16, __half, wmma::col_major>;
using HFragC  = wmma::fragment<wmma::accumulator, 16, 16, 16, float>;

// ----------------------------- converts --------------------------------------
__global__ void __launch_bounds__(256)
cvt_kernel(const float* __restrict__ src, __half* __restrict__ dst, int n)
{
    int i = (blockIdx.x * 256 + threadIdx.x) * 8;
    if (i >= n) return;
    float4 a = *(const float4*)(src + i);
    float4 b = *(const float4*)(src + i + 4);
    __half2 h0 = __floats2half2_rn(a.x, a.y);
    __half2 h1 = __floats2half2_rn(a.z, a.w);
    __half2 h2 = __floats2half2_rn(b.x, b.y);
    __half2 h3 = __floats2half2_rn(b.z, b.w);
    uint4 u;
    u.x = *(unsigned*)&h0; u.y = *(unsigned*)&h1;
    u.z = *(unsigned*)&h2; u.w = *(unsigned*)&h3;
    *(uint4*)(dst + i) = u;
}

// ----------------------------- means / gate ----------------------------------
__global__ void __launch_bounds__(256)
mean_kernel(const float* __restrict__ query, const float* __restrict__ memory)
{
    using namespace cfg;
    const int b = blockIdx.y;
    const int d = blockIdx.x * blockDim.x + threadIdx.x;

    const float* qp = query + (size_t)b * T * D + d;
    float s0 = 0.f, s1 = 0.f, s2 = 0.f, s3 = 0.f;
    for (int t = 0; t < T; t += 4) {
        s0 += qp[(size_t)(t + 0) * D];
        s1 += qp[(size_t)(t + 1) * D];
        s2 += qp[(size_t)(t + 2) * D];
        s3 += qp[(size_t)(t + 3) * D];
    }
    g_memin[b * 2 * D + d] = ((s0 + s1) + (s2 + s3)) * (1.0f / T);

    const float* mp = memory + (size_t)b * M * D + d;
    float u0 = 0.f, u1 = 0.f;
    for (int m = 0; m < M; m += 2) {
        u0 += mp[(size_t)(m + 0) * D];
        u1 += mp[(size_t)(m + 1) * D];
    }
    g_memin[b * 2 * D + D + d] = (u0 + u1) * (1.0f / M);
}

__global__ void __launch_bounds__(256)
gate_vals_kernel(const float* __restrict__ Wg, const float* __restrict__ bg)
{
    using namespace cfg;
    const int b = blockIdx.y;
    const int j = blockIdx.x * blockDim.x + threadIdx.x;
    const float* mi = g_memin + b * 2 * D;

    float a0 = 0.f, a1 = 0.f, a2 = 0.f, a3 = 0.f;
    for (int i = 0; i < 2 * D; i += 4) {
        a0 += mi[i + 0] * Wg[(size_t)(i + 0) * D + j];
        a1 += mi[i + 1] * Wg[(size_t)(i + 1) * D + j];
        a2 += mi[i + 2] * Wg[(size_t)(i + 2) * D + j];
        a3 += mi[i + 3] * Wg[(size_t)(i + 3) * D + j];
    }
    float acc = bg[j] + ((a0 + a1) + (a2 + a3));
    g_gatevals[b * D + j] = 1.0f / (1.0f + expf(-acc));
}

__global__ void gate_reduce_kernel()
{
    using namespace cfg;
    __shared__ float red[1024];
    const int t = threadIdx.x;
    red[t] = g_gatevals[t] + g_gatevals[t + 1024] +
             g_gatevals[t + 2048] + g_gatevals[t + 3072];
    __syncthreads();
    for (int s = 512; s > 0; s >>= 1) {
        if (t < s) red[t] += red[t + s];
        __syncthreads();
    }
    if (t == 0) g_scale_val = red[0] * (1.0f / (B * D)) * 0.125f;
}

// ----------------------------- fp16 GEMM, 64x64 warp tiles -------------------
// C = A[8192,1024] @ W[1024,1024] + bias.  CTA tile 128x256, BK=32,
// 8 warps (2x4), warp tile 64x64 = 4x4 m16n16k16 fragments.
template <bool HALF_OUT>
__device__ __forceinline__ void gemm_body_h(
    const __half* __restrict__ A, const __half* __restrict__ W,
    const float* __restrict__ bias, __half* __restrict__ Ch,
    float* __restrict__ Cf)
{
    using namespace cfg;
    extern __shared__ __half gsm[];
    __half* As[2] = { gsm + G_AS_OFF, gsm + G_AS_OFF + G_AS_SZ };
    __half* Bs[2] = { gsm + G_BS_OFF, gsm + G_BS_OFF + G_BS_SZ };
    float*  idxm  = (float*)(gsm + G_IDX_OFF);

    const int tid = threadIdx.x;
    const int warpId = tid >> 5;
    const int wr = warpId >> 2;            // 0..1  (64-row group)
    const int wc = warpId & 3;             // 0..3  (64-col group)
    const int m0 = blockIdx.y * 128;
    const int n0 = blockIdx.x * 256;

    idxm[tid] = (float)tid;                // (row<<4 | col) within 16x16 tile

    auto issue_tile = [&](int k0, int buf) {
        __half* ab = As[buf];
        __half* bb = Bs[buf];
#pragma unroll
        for (int t = 0; t < 2; t++) {      // A: 128 x 32 halves
            int idx = tid + t * 256;
            int r = idx >> 2, c = (idx & 3) * 8;
            cp_async16(ab + r * GA_STRIDE + c, A + (size_t)(m0 + r) * D + k0 + c);
        }
#pragma unroll
        for (int t = 0; t < 4; t++) {      // B: 32 x 256 halves
            int idx = tid + t * 256;
            int r = idx >> 5, c = (idx & 31) * 8;
            cp_async16(bb + r * GB_STRIDE + c, W + (size_t)(k0 + r) * D + n0 + c);
        }
        cp_commit();
    };

    HFragC acc[4][4];
#pragma unroll
    for (int i = 0; i < 4; i++)
#pragma unroll
        for (int j = 0; j < 4; j++) wmma::fill_fragment(acc[i][j], 0.f);

    issue_tile(0, 0);
    __syncthreads();
    HFragC idxf;
    wmma::load_matrix_sync(idxf, idxm, 16, wmma::mem_row_major);

    constexpr int NIT = cfg::D / 32;       // 32 stages
    for (int kt = 0; kt < NIT; kt++) {
        const int buf = kt & 1;
        if (kt + 1 < NIT) issue_tile((kt + 1) * 32, buf ^ 1);
        if (kt + 1 < NIT) cp_wait<1>(); else cp_wait<0>();
        __syncthreads();

#pragma unroll
        for (int kk = 0; kk < 2; kk++) {
            HFragA af[4];
#pragma unroll
            for (int i = 0; i < 4; i++)
                wmma::load_matrix_sync(af[i],
                    As[buf] + (64 * wr + 16 * i) * GA_STRIDE + 16 * kk, GA_STRIDE);
#pragma unroll
            for (int j = 0; j < 4; j++) {
                HFragBr bf;
                wmma::load_matrix_sync(bf,
                    Bs[buf] + (16 * kk) * GB_STRIDE + 64 * wc + 16 * j, GB_STRIDE);
#pragma unroll
                for (int i = 0; i < 4; i++)
                    wmma::mma_sync(acc[i][j], af[i], bf, acc[i][j]);
            }
        }
        __syncthreads();
    }

#pragma unroll
    for (int i = 0; i < 4; i++)
#pragma unroll
        for (int j = 0; j < 4; j++) {
            const int rbase = m0 + 64 * wr + 16 * i;
            const int cbase = n0 + 64 * wc + 16 * j;
            if (HALF_OUT) {
#pragma unroll
                for (int e = 0; e < 8; e++) {
                    int v = (int)idxf.x[e];
                    int r = v >> 4, c = v & 15;
                    Ch[(size_t)(rbase + r) * D + cbase + c] =
                        __float2half(acc[i][j].x[e] + __ldg(&bias[cbase + c]));
                }
            } else {
#pragma unroll
                for (int e = 0; e < 8; e++)
                    acc[i][j].x[e] += __ldg(&bias[cbase + ((int)idxf.x[e] & 15)]);
                wmma::store_matrix_sync(Cf + (size_t)rbase * D + cbase,
                                        acc[i][j], D, wmma::mem_row_major);
            }
        }
}

__global__ void __launch_bounds__(256)
gemm_qkv_h_kernel(const float* __restrict__ bq, const float* __restrict__ bk,
                  const float* __restrict__ bv)
{
    const __half *A, *W; const float* bias; __half* C;
    if (blockIdx.z == 0)      { A = g_qh; W = g_Wqh; bias = bq; C = g_Qh; }
    else if (blockIdx.z == 1) { A = g_kh; W = g_Wkh; bias = bk; C = g_Kh; }
    else                      { A = g_vh; W = g_Wvh; bias = bv; C = g_Vh; }
    gemm_body_h<true>(A, W, bias, C, nullptr);
}

__global__ void __launch_bounds__(256)
gemm_out_kernel(const float* __restrict__ bo, float* __restrict__ out)
{
    gemm_body_h<false>(g_Oh, g_Woh, bo, nullptr, out);
}

// ----------------------------- fp16 flash, warp-local softmax ----------------
// grid (T/128, H, B), 256 threads = 8 warps; warp w owns rows 16w..16w+15.
// Only cross-warp data is K/V -> ONE __syncthreads per tile.
__global__ void __launch_bounds__(256)
flash_h_kernel(float* dummy)
{
    using namespace cfg;
    extern __shared__ char smraw[];
    __half* Ks  = (__half*)smraw;
    __half* Vs  = Ks + FL_KS_H;
    __half* Ps  = Vs + FL_VS_H;
    float*  Ss  = (float*)(Ps + FL_PS_H);
    float*  m_s = Ss + FL_SS_F;
    float*  l_s    = m_s + 128;
    float*  corr_s = l_s + 128;
    float*  idxm   = corr_s + 128;

    const int b = blockIdx.z, h = blockIdx.y, q0 = blockIdx.x * 128;
    const int tid = threadIdx.x;
    const int w = tid >> 5;
    const int lane = tid & 31;
    const float gscale = g_scale_val;

    const __half* Kp = g_Kh + (size_t)b * S * D + h * DH;
    const __half* Vp = g_Vh + (size_t)b * S * D + h * DH;

    idxm[tid] = (float)tid;
    if (tid < 128) { m_s[tid] = -INFINITY; l_s[tid] = 0.f; }

    // stage Q tile (128 x 64 halves) into Ps: warp w stages its own 16 rows
    {
        const int r = tid >> 1, half_ = tid & 1;
        const __half* src = g_Qh + (size_t)(b * T + q0 + r) * D + h * DH + half_ * 32;
        __half* dst = &Ps[r * LDH + half_ * 32];
#pragma unroll
        for (int jj = 0; jj < 4; jj++)
            *(uint4*)(dst + jj * 8) = *(const uint4*)(src + jj * 8);
    }
    __syncthreads();            // m/l init + idxm + Q staging visible

    HFragC idxf;
    wmma::load_matrix_sync(idxf, idxm, 16, wmma::mem_row_major);

    HFragA qf[4];
#pragma unroll
    for (int k = 0; k < 4; k++)
        wmma::load_matrix_sync(qf[k], &Ps[(16 * w) * LDH + 16 * k], LDH);
    HFragC of[4];
#pragma unroll
    for (int j = 0; j < 4; j++) wmma::fill_fragment(of[j], 0.f);

    auto issue_kv = [&](int s0, int buf) {
        __half* kb = Ks + buf * 64 * LDH;
        __half* vb = Vs + buf * 64 * LDH;
#pragma unroll
        for (int t = 0; t < 2; t++) {
            int c = tid + t * 256;
            int row = c >> 3, col = (c & 7) * 8;
            cp_async16(&kb[row * LDH + col], Kp + (size_t)(s0 + row) * D + col);
        }
#pragma unroll
        for (int t = 0; t < 2; t++) {
            int c = tid + t * 256;
            int row = c >> 3, col = (c & 7) * 8;
            cp_async16(&vb[row * LDH + col], Vp + (size_t)(s0 + row) * D + col);
        }
        cp_commit();
    };

    issue_kv(0, 0);

    // softmax lane mapping: lane pair handles one row
    const int srow  = 16 * w + (lane >> 1);
    const int shalf = lane & 1;

    constexpr int NT = cfg::S / 64;
    for (int it = 0; it < NT; it++) {
        const int buf = it & 1;
        cp_wait<0>();            // tile `it` data arrived
        __syncthreads();         // all warps done with the other buffer
        if (it + 1 < NT) issue_kv((it + 1) * 64, buf ^ 1);

        // ---- S = Q K^T (rows 16w, warp-local output)
        const __half* kb = Ks + buf * 64 * LDH;
        HFragC sf[4];
#pragma unroll
        for (int j = 0; j < 4; j++) wmma::fill_fragment(sf[j], 0.f);
#pragma unroll
        for (int k = 0; k < 4; k++) {
#pragma unroll
            for (int j = 0; j < 4; j++) {
                HFragBc bf;
                wmma::load_matrix_sync(bf, &kb[(16 * j) * LDH + 16 * k], LDH);
                wmma::mma_sync(sf[j], qf[k], bf, sf[j]);
            }
        }
#pragma unroll
        for (int j = 0; j < 4; j++)
            wmma::store_matrix_sync(&Ss[(16 * w) * LDS + 16 * j], sf[j],
                                    LDS, wmma::mem_row_major);
        __syncwarp();

        // ---- warp-local online softmax (2 lanes per row, 32 cols each)
        {
            float* row = &Ss[srow * LDS + shalf * 32];
            __half* prow = &Ps[srow * LDH + shalf * 32];
            float v[32];
#pragma unroll
            for (int jj = 0; jj < 8; jj++) {
                float4 x = *(float4*)(row + jj * 4);
                v[jj * 4 + 0] = x.x * gscale; v[jj * 4 + 1] = x.y * gscale;
                v[jj * 4 + 2] = x.z * gscale; v[jj * 4 + 3] = x.w * gscale;
            }
            float mx = v[0];
#pragma unroll
            for (int i = 1; i < 32; i++) mx = fmaxf(mx, v[i]);
            mx = fmaxf(mx, __shfl_xor_sync(0xffffffffu, mx, 1));

            const float mold = m_s[srow];
            const float nm = fmaxf(mold, mx);
            float sum = 0.f;
#pragma unroll
            for (int i = 0; i < 32; i++) { v[i] = __expf(v[i] - nm); sum += v[i]; }
#pragma unroll
            for (int jj = 0; jj < 16; jj++)
                *(__half2*)(prow + jj * 2) = __floats2half2_rn(v[jj * 2], v[jj * 2 + 1]);
            sum += __shfl_xor_sync(0xffffffffu, sum, 1);
            if (shalf == 0) {
                float corr = __expf(mold - nm);
                l_s[srow] = l_s[srow] * corr + sum;
                m_s[srow] = nm;
                corr_s[srow] = corr;
            }
        }
        __syncwarp();

        // ---- rescale O accumulators (warp-local corr)
#pragma unroll
        for (int j = 0; j < 4; j++)
#pragma unroll
            for (int e = 0; e < 8; e++)
                of[j].x[e] *= corr_s[16 * w + ((int)idxf.x[e] >> 4)];

        // ---- O += P V  (P rows 16w warp-local; V shared, covered by barrier)
        const __half* vb = Vs + buf * 64 * LDH;
#pragma unroll
        for (int k = 0; k < 4; k++) {
            HFragA pf;
            wmma::load_matrix_sync(pf, &Ps[(16 * w) * LDH + 16 * k], LDH);
#pragma unroll
            for (int j = 0; j < 4; j++) {
                HFragBr vf;
                wmma::load_matrix_sync(vf, &vb[(16 * k) * LDH + 16 * j], LDH);
                wmma::mma_sync(of[j], pf, vf, of[j]);
            }
        }
    }

    // epilogue (warp-local normalize + scatter store)
    if (shalf == 0) corr_s[srow] = 1.0f / l_s[srow];
    __syncwarp();
#pragma unroll
    for (int j = 0; j < 4; j++) {
#pragma unroll
        for (int e = 0; e < 8; e++) {
            int v = (int)idxf.x[e];
            int r = v >> 4, c = v & 15;
            g_Oh[(size_t)(b * T + q0 + 16 * w + r) * D + h * DH + 16 * j + c] =
                __float2half(of[j].x[e] * corr_s[16 * w + r]);
        }
    }
    (void)dummy;
}

// ----------------------------- launch ----------------------------------------
extern "C" void kernel_launch(void* const* d_in, const int* in_sizes, int n_in,
                              void* d_out, int out_size)
{
    using namespace cfg;
    (void)in_sizes; (void)n_in; (void)out_size;

    const float* query  = (const float*)d_in[0];
    const float* key    = (const float*)d_in[1];
    const float* value  = (const float*)d_in[2];
    const float* memory = (const float*)d_in[3];
    const float* Wq = (const float*)d_in[4];
    const float* bq = (const float*)d_in[5];
    const float* Wk = (const float*)d_in[6];
    const float* bk = (const float*)d_in[7];
    const float* Wv = (const float*)d_in[8];
    const float* bv = (const float*)d_in[9];
    const float* Wo = (const float*)d_in[10];
    const float* bo = (const float*)d_in[11];
    const float* Wg = (const float*)d_in[12];
    const float* bg = (const float*)d_in[13];
    float* out = (float*)d_out;

    void *qh, *kh, *vh, *wqh, *wkh, *wvh, *woh;
    cudaGetSymbolAddress(&qh,  g_qh);
    cudaGetSymbolAddress(&kh,  g_kh);
    cudaGetSymbolAddress(&vh,  g_vh);
    cudaGetSymbolAddress(&wqh, g_Wqh);
    cudaGetSymbolAddress(&wkh, g_Wkh);
    cudaGetSymbolAddress(&wvh, g_Wvh);
    cudaGetSymbolAddress(&woh, g_Woh);

    cudaFuncSetAttribute(flash_h_kernel,
                         cudaFuncAttributeMaxDynamicSharedMemorySize, FL_BYTES);
    cudaFuncSetAttribute(gemm_qkv_h_kernel,
                         cudaFuncAttributeMaxDynamicSharedMemorySize, G_SMEM);
    cudaFuncSetAttribute(gemm_out_kernel,
                         cudaFuncAttributeMaxDynamicSharedMemorySize, G_SMEM);

    // gate path (fp32, independent)
    mean_kernel<<<dim3(D / 256, B), 256>>>(query, memory);
    gate_vals_kernel<<<dim3(D / 256, B), 256>>>(Wg, bg);
    gate_reduce_kernel<<<1, 1024>>>();

    // convert inputs + weights to half
    const int nBig = BT * D;
    const int nW   = D * D;
    cvt_kernel<<<nBig / (256 * 8), 256>>>(query, (__half*)qh, nBig);
    cvt_kernel<<<nBig / (256 * 8), 256>>>(key,   (__half*)kh, nBig);
    cvt_kernel<<<nBig / (256 * 8), 256>>>(value, (__half*)vh, nBig);
    cvt_kernel<<<nW / (256 * 8), 256>>>(Wq, (__half*)wqh, nW);
    cvt_kernel<<<nW / (256 * 8), 256>>>(Wk, (__half*)wkh, nW);
    cvt_kernel<<<nW / (256 * 8), 256>>>(Wv, (__half*)wvh, nW);
    cvt_kernel<<<nW / (256 * 8), 256>>>(Wo, (__half*)woh, nW);

    // fused QKV projections (fp16 tensor cores, 64x64 warp tiles)
    gemm_qkv_h_kernel<<<dim3(D / 256, BT / 128, 3), 256, G_SMEM>>>(bq, bk, bv);

    // attention (fp16 tensor cores, 1 barrier/tile)
    flash_h_kernel<<<dim3(T / 128, H, B), 256, FL_BYTES>>>(nullptr);

    // output projection -> d_out (fp32 out)
    gemm_out_kernel<<<dim3(D / 256, BT / 128), 256, G_SMEM>>>(bo, out);
}

// round 12
// speedup vs baseline: 1.0941x; 1.0941x over previous
#include <cuda_runtime.h>
#include <cuda_fp16.h>
#include <mma.h>
#include <math.h>
#include <stdint.h>

using namespace nvcuda;

// ---------------------------------------------------------------------------
// MemoryGatedAttention  (B=4, T=S=2048, D=1024, H=16, DH=64, M=64)
// Round 12 (re-bench of R11 after infra failure): R7's proven GEMM
// (64x32 warp tiles, 2 CTA/SM) + R10's flash (warp-local softmax,
// 1 block barrier per K/V tile). Single attributable delta vs R7 (1060us).
// ---------------------------------------------------------------------------

namespace cfg {
constexpr int B  = 4;
constexpr int T  = 2048;
constexpr int S  = 2048;
constexpr int D  = 1024;
constexpr int H  = 16;
constexpr int DH = 64;
constexpr int M  = 64;
constexpr int BT = B * T;
// flash smem (bytes)
constexpr int LDH = 72;
constexpr int LDS = 68;
constexpr int FL_KS_H   = 2 * 64 * LDH;
constexpr int FL_VS_H   = 2 * 64 * LDH;
constexpr int FL_PS_H   = 128 * LDH;
constexpr int FL_SS_F   = 128 * LDS;
constexpr int FL_BYTES  = (FL_KS_H + FL_VS_H + FL_PS_H) * 2
                        + FL_SS_F * 4 + (3 * 128 + 256) * 4;   // ~92.7KB
}

// ----------------------------- scratch --------------------------------------
__device__ __half g_qh[cfg::BT * cfg::D];
__device__ __half g_kh[cfg::BT * cfg::D];
__device__ __half g_vh[cfg::BT * cfg::D];
__device__ __half g_Wqh[cfg::D * cfg::D];
__device__ __half g_Wkh[cfg::D * cfg::D];
__device__ __half g_Wvh[cfg::D * cfg::D];
__device__ __half g_Woh[cfg::D * cfg::D];
__device__ __half g_Qh[cfg::BT * cfg::D];
__device__ __half g_Kh[cfg::BT * cfg::D];
__device__ __half g_Vh[cfg::BT * cfg::D];
__device__ __half g_Oh[cfg::BT * cfg::D];
__device__ float  g_memin[cfg::B * 2 * cfg::D];
__device__ float  g_gatevals[cfg::B * cfg::D];
__device__ float  g_scale_val;

// ----------------------------- cp.async helpers ------------------------------
__device__ __forceinline__ void cp_async16(void* smem_dst, const void* gmem_src) {
    unsigned sa = (unsigned)__cvta_generic_to_shared(smem_dst);
    asm volatile("cp.async.cg.shared.global [%0], [%1], 16;\n" :: "r"(sa), "l"(gmem_src));
}
__device__ __forceinline__ void cp_commit() {
    asm volatile("cp.async.commit_group;\n");
}
template <int N>
__device__ __forceinline__ void cp_wait() {
    asm volatile("cp.async.wait_group %0;\n" :: "n"(N));
}

// ----------------------------- fragment types --------------------------------
using HFragA  = wmma::fragment<wmma::matrix_a, 16, 16, 16, __half, wmma::row_major>;
using HFragBr = wmma::fragment<wmma::matrix_b, 16, 16, 16, __half, wmma::row_major>;
using HFragBc = wmma::fragment<wmma::matrix_b, 16, 16, 16, __half, wmma::col_major>;
using HFragC  = wmma::fragment<wmma::accumulator, 16, 16, 16, float>;

// ----------------------------- converts --------------------------------------
__global__ void __launch_bounds__(256)
cvt_kernel(const float* __restrict__ src, __half* __restrict__ dst, int n)
{
    int i = (blockIdx.x * 256 + threadIdx.x) * 8;
    if (i >= n) return;
    float4 a = *(const float4*)(src + i);
    float4 b = *(const float4*)(src + i + 4);
    __half2 h0 = __floats2half2_rn(a.x, a.y);
    __half2 h1 = __floats2half2_rn(a.z, a.w);
    __half2 h2 = __floats2half2_rn(b.x, b.y);
    __half2 h3 = __floats2half2_rn(b.z, b.w);
    uint4 u;
    u.x = *(unsigned*)&h0; u.y = *(unsigned*)&h1;
    u.z = *(unsigned*)&h2; u.w = *(unsigned*)&h3;
    *(uint4*)(dst + i) = u;
}

// ----------------------------- means / gate ----------------------------------
__global__ void __launch_bounds__(256)
mean_kernel(const float* __restrict__ query, const float* __restrict__ memory)
{
    using namespace cfg;
    const int b = blockIdx.y;
    const int d = blockIdx.x * blockDim.x + threadIdx.x;

    const float* qp = query + (size_t)b * T * D + d;
    float s0 = 0.f, s1 = 0.f, s2 = 0.f, s3 = 0.f;
    for (int t = 0; t < T; t += 4) {
        s0 += qp[(size_t)(t + 0) * D];
        s1 += qp[(size_t)(t + 1) * D];
        s2 += qp[(size_t)(t + 2) * D];
        s3 += qp[(size_t)(t + 3) * D];
    }
    g_memin[b * 2 * D + d] = ((s0 + s1) + (s2 + s3)) * (1.0f / T);

    const float* mp = memory + (size_t)b * M * D + d;
    float u0 = 0.f, u1 = 0.f;
    for (int m = 0; m < M; m += 2) {
        u0 += mp[(size_t)(m + 0) * D];
        u1 += mp[(size_t)(m + 1) * D];
    }
    g_memin[b * 2 * D + D + d] = (u0 + u1) * (1.0f / M);
}

__global__ void __launch_bounds__(256)
gate_vals_kernel(const float* __restrict__ Wg, const float* __restrict__ bg)
{
    using namespace cfg;
    const int b = blockIdx.y;
    const int j = blockIdx.x * blockDim.x + threadIdx.x;
    const float* mi = g_memin + b * 2 * D;

    float a0 = 0.f, a1 = 0.f, a2 = 0.f, a3 = 0.f;
    for (int i = 0; i < 2 * D; i += 4) {
        a0 += mi[i + 0] * Wg[(size_t)(i + 0) * D + j];
        a1 += mi[i + 1] * Wg[(size_t)(i + 1) * D + j];
        a2 += mi[i + 2] * Wg[(size_t)(i + 2) * D + j];
        a3 += mi[i + 3] * Wg[(size_t)(i + 3) * D + j];
    }
    float acc = bg[j] + ((a0 + a1) + (a2 + a3));
    g_gatevals[b * D + j] = 1.0f / (1.0f + expf(-acc));
}

__global__ void gate_reduce_kernel()
{
    using namespace cfg;
    __shared__ float red[1024];
    const int t = threadIdx.x;
    red[t] = g_gatevals[t] + g_gatevals[t + 1024] +
             g_gatevals[t + 2048] + g_gatevals[t + 3072];
    __syncthreads();
    for (int s = 512; s > 0; s >>= 1) {
        if (t < s) red[t] += red[t + s];
        __syncthreads();
    }
    if (t == 0) g_scale_val = red[0] * (1.0f / (B * D)) * 0.125f;
}

// ----------------------------- fp16 GEMM (R7: 64x32 warp tiles) --------------
// C = A[8192,1024] @ W[1024,1024] + bias.  128x128 block, BK=32, 8 warps(2x4),
// warp tile 64x32 = 4x2 m16n16k16 fragments. cp.async double buffered.
template <bool HALF_OUT>
__device__ __forceinline__ void gemm_body_h(
    const __half* __restrict__ A, const __half* __restrict__ W,
    const float* __restrict__ bias, __half* __restrict__ Ch,
    float* __restrict__ Cf)
{
    using namespace cfg;
    __shared__ __half As[2][128][40];      // [m][k] pad 8 halves
    __shared__ __half Bs[2][32][136];      // [k][n] pad 8 halves
    __shared__ float idxm[256];

    const int tid = threadIdx.x;
    const int warpId = tid >> 5;
    const int wr = warpId >> 2;            // 0..1
    const int wc = warpId & 3;             // 0..3
    const int m0 = blockIdx.y * 128;
    const int n0 = blockIdx.x * 128;

    idxm[tid] = (float)tid;                // (row<<4 | col) within 16x16 tile

    auto issue_tile = [&](int k0, int buf) {
#pragma unroll
        for (int t = 0; t < 2; t++) {
            int c = tid + t * 256;
            int r = c >> 2, cc = (c & 3) * 8;
            cp_async16(&As[buf][r][cc], A + (size_t)(m0 + r) * D + k0 + cc);
        }
#pragma unroll
        for (int t = 0; t < 2; t++) {
            int c = tid + t * 256;
            int r = c >> 4, cc = (c & 15) * 8;
            cp_async16(&Bs[buf][r][cc], W + (size_t)(k0 + r) * D + n0 + cc);
        }
        cp_commit();
    };

    HFragC acc[4][2];
#pragma unroll
    for (int i = 0; i < 4; i++)
#pragma unroll
        for (int j = 0; j < 2; j++) wmma::fill_fragment(acc[i][j], 0.f);

    issue_tile(0, 0);
    __syncthreads();
    HFragC idxf;
    wmma::load_matrix_sync(idxf, idxm, 16, wmma::mem_row_major);

    constexpr int NIT = cfg::D / 32;       // 32 stages
    for (int kt = 0; kt < NIT; kt++) {
        const int buf = kt & 1;
        if (kt + 1 < NIT) issue_tile((kt + 1) * 32, buf ^ 1);
        if (kt + 1 < NIT) cp_wait<1>(); else cp_wait<0>();
        __syncthreads();

#pragma unroll
        for (int kk = 0; kk < 2; kk++) {
            HFragA af[4];
#pragma unroll
            for (int i = 0; i < 4; i++)
                wmma::load_matrix_sync(af[i], &As[buf][64 * wr + 16 * i][16 * kk], 40);
            HFragBr bf[2];
#pragma unroll
            for (int j = 0; j < 2; j++)
                wmma::load_matrix_sync(bf[j], &Bs[buf][16 * kk][32 * wc + 16 * j], 136);
#pragma unroll
            for (int i = 0; i < 4; i++)
#pragma unroll
                for (int j = 0; j < 2; j++)
                    wmma::mma_sync(acc[i][j], af[i], bf[j], acc[i][j]);
        }
        __syncthreads();
    }

#pragma unroll
    for (int i = 0; i < 4; i++)
#pragma unroll
        for (int j = 0; j < 2; j++) {
            const int rbase = m0 + 64 * wr + 16 * i;
            const int cbase = n0 + 32 * wc + 16 * j;
            if (HALF_OUT) {
#pragma unroll
                for (int e = 0; e < 8; e++) {
                    int v = (int)idxf.x[e];
                    int r = v >> 4, c = v & 15;
                    Ch[(size_t)(rbase + r) * D + cbase + c] =
                        __float2half(acc[i][j].x[e] + __ldg(&bias[cbase + c]));
                }
            } else {
#pragma unroll
                for (int e = 0; e < 8; e++)
                    acc[i][j].x[e] += __ldg(&bias[cbase + ((int)idxf.x[e] & 15)]);
                wmma::store_matrix_sync(Cf + (size_t)rbase * D + cbase,
                                        acc[i][j], D, wmma::mem_row_major);
            }
        }
}

__global__ void __launch_bounds__(256)
gemm_qkv_h_kernel(const float* __restrict__ bq, const float* __restrict__ bk,
                  const float* __restrict__ bv)
{
    const __half *A, *W; const float* bias; __half* C;
    if (blockIdx.z == 0)      { A = g_qh; W = g_Wqh; bias = bq; C = g_Qh; }
    else if (blockIdx.z == 1) { A = g_kh; W = g_Wkh; bias = bk; C = g_Kh; }
    else                      { A = g_vh; W = g_Wvh; bias = bv; C = g_Vh; }
    gemm_body_h<true>(A, W, bias, C, nullptr);
}

__global__ void __launch_bounds__(256)
gemm_out_kernel(const float* __restrict__ bo, float* __restrict__ out)
{
    gemm_body_h<false>(g_Oh, g_Woh, bo, nullptr, out);
}

// ----------------------------- fp16 flash, warp-local softmax ----------------
// grid (T/128, H, B), 256 threads = 8 warps; warp w owns rows 16w..16w+15.
// Only cross-warp data is K/V -> ONE __syncthreads per tile.
__global__ void __launch_bounds__(256)
flash_h_kernel(float* dummy)
{
    using namespace cfg;
    extern __shared__ char smraw[];
    __half* Ks  = (__half*)smraw;
    __half* Vs  = Ks + FL_KS_H;
    __half* Ps  = Vs + FL_VS_H;
    float*  Ss  = (float*)(Ps + FL_PS_H);
    float*  m_s = Ss + FL_SS_F;
    float*  l_s    = m_s + 128;
    float*  corr_s = l_s + 128;
    float*  idxm   = corr_s + 128;

    const int b = blockIdx.z, h = blockIdx.y, q0 = blockIdx.x * 128;
    const int tid = threadIdx.x;
    const int w = tid >> 5;
    const int lane = tid & 31;
    const float gscale = g_scale_val;

    const __half* Kp = g_Kh + (size_t)b * S * D + h * DH;
    const __half* Vp = g_Vh + (size_t)b * S * D + h * DH;

    idxm[tid] = (float)tid;
    if (tid < 128) { m_s[tid] = -INFINITY; l_s[tid] = 0.f; }

    // stage Q tile (128 x 64 halves) into Ps
    {
        const int r = tid >> 1, half_ = tid & 1;
        const __half* src = g_Qh + (size_t)(b * T + q0 + r) * D + h * DH + half_ * 32;
        __half* dst = &Ps[r * LDH + half_ * 32];
#pragma unroll
        for (int jj = 0; jj < 4; jj++)
            *(uint4*)(dst + jj * 8) = *(const uint4*)(src + jj * 8);
    }
    __syncthreads();            // m/l init + idxm + Q staging visible

    HFragC idxf;
    wmma::load_matrix_sync(idxf, idxm, 16, wmma::mem_row_major);

    HFragA qf[4];
#pragma unroll
    for (int k = 0; k < 4; k++)
        wmma::load_matrix_sync(qf[k], &Ps[(16 * w) * LDH + 16 * k], LDH);
    HFragC of[4];
#pragma unroll
    for (int j = 0; j < 4; j++) wmma::fill_fragment(of[j], 0.f);

    auto issue_kv = [&](int s0, int buf) {
        __half* kb = Ks + buf * 64 * LDH;
        __half* vb = Vs + buf * 64 * LDH;
#pragma unroll
        for (int t = 0; t < 2; t++) {
            int c = tid + t * 256;
            int row = c >> 3, col = (c & 7) * 8;
            cp_async16(&kb[row * LDH + col], Kp + (size_t)(s0 + row) * D + col);
        }
#pragma unroll
        for (int t = 0; t < 2; t++) {
            int c = tid + t * 256;
            int row = c >> 3, col = (c & 7) * 8;
            cp_async16(&vb[row * LDH + col], Vp + (size_t)(s0 + row) * D + col);
        }
        cp_commit();
    };

    issue_kv(0, 0);

    // softmax lane mapping: lane pair handles one row
    const int srow  = 16 * w + (lane >> 1);
    const int shalf = lane & 1;

    constexpr int NT = cfg::S / 64;
    for (int it = 0; it < NT; it++) {
        const int buf = it & 1;
        cp_wait<0>();            // tile `it` data arrived
        __syncthreads();         // all warps done with the other buffer
        if (it + 1 < NT) issue_kv((it + 1) * 64, buf ^ 1);

        // ---- S = Q K^T (rows 16w, warp-local output)
        const __half* kb = Ks + buf * 64 * LDH;
        HFragC sf[4];
#pragma unroll
        for (int j = 0; j < 4; j++) wmma::fill_fragment(sf[j], 0.f);
#pragma unroll
        for (int k = 0; k < 4; k++) {
#pragma unroll
            for (int j = 0; j < 4; j++) {
                HFragBc bf;
                wmma::load_matrix_sync(bf, &kb[(16 * j) * LDH + 16 * k], LDH);
                wmma::mma_sync(sf[j], qf[k], bf, sf[j]);
            }
        }
#pragma unroll
        for (int j = 0; j < 4; j++)
            wmma::store_matrix_sync(&Ss[(16 * w) * LDS + 16 * j], sf[j],
                                    LDS, wmma::mem_row_major);
        __syncwarp();

        // ---- warp-local online softmax (2 lanes per row, 32 cols each)
        {
            float* row = &Ss[srow * LDS + shalf * 32];
            __half* prow = &Ps[srow * LDH + shalf * 32];
            float v[32];
#pragma unroll
            for (int jj = 0; jj < 8; jj++) {
                float4 x = *(float4*)(row + jj * 4);
                v[jj * 4 + 0] = x.x * gscale; v[jj * 4 + 1] = x.y * gscale;
                v[jj * 4 + 2] = x.z * gscale; v[jj * 4 + 3] = x.w * gscale;
            }
            float mx = v[0];
#pragma unroll
            for (int i = 1; i < 32; i++) mx = fmaxf(mx, v[i]);
            mx = fmaxf(mx, __shfl_xor_sync(0xffffffffu, mx, 1));

            const float mold = m_s[srow];
            const float nm = fmaxf(mold, mx);
            float sum = 0.f;
#pragma unroll
            for (int i = 0; i < 32; i++) { v[i] = __expf(v[i] - nm); sum += v[i]; }
#pragma unroll
            for (int jj = 0; jj < 16; jj++)
                *(__half2*)(prow + jj * 2) = __floats2half2_rn(v[jj * 2], v[jj * 2 + 1]);
            sum += __shfl_xor_sync(0xffffffffu, sum, 1);
            if (shalf == 0) {
                float corr = __expf(mold - nm);
                l_s[srow] = l_s[srow] * corr + sum;
                m_s[srow] = nm;
                corr_s[srow] = corr;
            }
        }
        __syncwarp();

        // ---- rescale O accumulators (warp-local corr)
#pragma unroll
        for (int j = 0; j < 4; j++)
#pragma unroll
            for (int e = 0; e < 8; e++)
                of[j].x[e] *= corr_s[16 * w + ((int)idxf.x[e] >> 4)];

        // ---- O += P V  (P rows 16w warp-local; V shared, covered by barrier)
        const __half* vb = Vs + buf * 64 * LDH;
#pragma unroll
        for (int k = 0; k < 4; k++) {
            HFragA pf;
            wmma::load_matrix_sync(pf, &Ps[(16 * w) * LDH + 16 * k], LDH);
#pragma unroll
            for (int j = 0; j < 4; j++) {
                HFragBr vf;
                wmma::load_matrix_sync(vf, &vb[(16 * k) * LDH + 16 * j], LDH);
                wmma::mma_sync(of[j], pf, vf, of[j]);
            }
        }
    }

    // epilogue (warp-local normalize + scatter store)
    if (shalf == 0) corr_s[srow] = 1.0f / l_s[srow];
    __syncwarp();
#pragma unroll
    for (int j = 0; j < 4; j++) {
#pragma unroll
        for (int e = 0; e < 8; e++) {
            int v = (int)idxf.x[e];
            int r = v >> 4, c = v & 15;
            g_Oh[(size_t)(b * T + q0 + 16 * w + r) * D + h * DH + 16 * j + c] =
                __float2half(of[j].x[e] * corr_s[16 * w + r]);
        }
    }
    (void)dummy;
}

// ----------------------------- launch ----------------------------------------
extern "C" void kernel_launch(void* const* d_in, const int* in_sizes, int n_in,
                              void* d_out, int out_size)
{
    using namespace cfg;
    (void)in_sizes; (void)n_in; (void)out_size;

    const float* query  = (const float*)d_in[0];
    const float* key    = (const float*)d_in[1];
    const float* value  = (const float*)d_in[2];
    const float* memory = (const float*)d_in[3];
    const float* Wq = (const float*)d_in[4];
    const float* bq = (const float*)d_in[5];
    const float* Wk = (const float*)d_in[6];
    const float* bk = (const float*)d_in[7];
    const float* Wv = (const float*)d_in[8];
    const float* bv = (const float*)d_in[9];
    const float* Wo = (const float*)d_in[10];
    const float* bo = (const float*)d_in[11];
    const float* Wg = (const float*)d_in[12];
    const float* bg = (const float*)d_in[13];
    float* out = (float*)d_out;

    void *qh, *kh, *vh, *wqh, *wkh, *wvh, *woh;
    cudaGetSymbolAddress(&qh,  g_qh);
    cudaGetSymbolAddress(&kh,  g_kh);
    cudaGetSymbolAddress(&vh,  g_vh);
    cudaGetSymbolAddress(&wqh, g_Wqh);
    cudaGetSymbolAddress(&wkh, g_Wkh);
    cudaGetSymbolAddress(&wvh, g_Wvh);
    cudaGetSymbolAddress(&woh, g_Woh);

    cudaFuncSetAttribute(flash_h_kernel,
                         cudaFuncAttributeMaxDynamicSharedMemorySize, FL_BYTES);

    // gate path (fp32, independent)
    mean_kernel<<<dim3(D / 256, B), 256>>>(query, memory);
    gate_vals_kernel<<<dim3(D / 256, B), 256>>>(Wg, bg);
    gate_reduce_kernel<<<1, 1024>>>();

    // convert inputs + weights to half
    const int nBig = BT * D;
    const int nW   = D * D;
    cvt_kernel<<<nBig / (256 * 8), 256>>>(query, (__half*)qh, nBig);
    cvt_kernel<<<nBig / (256 * 8), 256>>>(key,   (__half*)kh, nBig);
    cvt_kernel<<<nBig / (256 * 8), 256>>>(value, (__half*)vh, nBig);
    cvt_kernel<<<nW / (256 * 8), 256>>>(Wq, (__half*)wqh, nW);
    cvt_kernel<<<nW / (256 * 8), 256>>>(Wk, (__half*)wkh, nW);
    cvt_kernel<<<nW / (256 * 8), 256>>>(Wv, (__half*)wvh, nW);
    cvt_kernel<<<nW / (256 * 8), 256>>>(Wo, (__half*)woh, nW);

    // fused QKV projections (fp16 tensor cores, 64x32 warp tiles)
    gemm_qkv_h_kernel<<<dim3(D / 128, BT / 128, 3), 256>>>(bq, bk, bv);

    // attention (fp16 tensor cores, 1 barrier/tile)
    flash_h_kernel<<<dim3(T / 128, H, B), 256, FL_BYTES>>>(nullptr);

    // output projection -> d_out (fp32 out)
    gemm_out_kernel<<<dim3(D / 128, BT / 128), 256>>>(bo, out);
}

// round 13
// speedup vs baseline: 1.3123x; 1.1994x over previous
#include <cuda_runtime.h>
#include <cuda_fp16.h>
#include <mma.h>
#include <math.h>
#include <stdint.h>

using namespace nvcuda;

// ---------------------------------------------------------------------------
// MemoryGatedAttention  (B=4, T=S=2048, D=1024, H=16, DH=64, M=64)
// Round 13: FA2-style flash with raw mma.sync.m16n8k16 + register softmax
// (no S/P smem round trip). GEMMs identical to R12 (1039us baseline).
// ---------------------------------------------------------------------------

namespace cfg {
constexpr int B  = 4;
constexpr int T  = 2048;
constexpr int S  = 2048;
constexpr int D  = 1024;
constexpr int H  = 16;
constexpr int DH = 64;
constexpr int M  = 64;
constexpr int BT = B * T;
// flash smem (halves): Qs[128*72] + Ks[2][64*72] + Vs[2][64*72]
constexpr int LDH = 72;
constexpr int QS_OFF = 0;
constexpr int QS_SZ  = 128 * LDH;              // 9216
constexpr int KS_OFF = QS_SZ;                  // 9216
constexpr int KS_SZ  = 64 * LDH;               // per buffer 4608
constexpr int VS_OFF = KS_OFF + 2 * KS_SZ;     // 18432
constexpr int FL_BYTES = (VS_OFF + 2 * KS_SZ) * 2;   // 55296 B
}

// ----------------------------- scratch --------------------------------------
__device__ __half g_qh[cfg::BT * cfg::D];
__device__ __half g_kh[cfg::BT * cfg::D];
__device__ __half g_vh[cfg::BT * cfg::D];
__device__ __half g_Wqh[cfg::D * cfg::D];
__device__ __half g_Wkh[cfg::D * cfg::D];
__device__ __half g_Wvh[cfg::D * cfg::D];
__device__ __half g_Woh[cfg::D * cfg::D];
__device__ __half g_Qh[cfg::BT * cfg::D];
__device__ __half g_Kh[cfg::BT * cfg::D];
__device__ __half g_Vh[cfg::BT * cfg::D];
__device__ __half g_Oh[cfg::BT * cfg::D];
__device__ float  g_memin[cfg::B * 2 * cfg::D];
__device__ float  g_gatevals[cfg::B * cfg::D];
__device__ float  g_scale_val;

// ----------------------------- low-level helpers -----------------------------
__device__ __forceinline__ void cp_async16(void* smem_dst, const void* gmem_src) {
    unsigned sa = (unsigned)__cvta_generic_to_shared(smem_dst);
    asm volatile("cp.async.cg.shared.global [%0], [%1], 16;\n" :: "r"(sa), "l"(gmem_src));
}
__device__ __forceinline__ void cp_commit() {
    asm volatile("cp.async.commit_group;\n");
}
template <int N>
__device__ __forceinline__ void cp_wait() {
    asm volatile("cp.async.wait_group %0;\n" :: "n"(N));
}
__device__ __forceinline__ void ldsm_x4(uint32_t* r, uint32_t addr) {
    asm volatile("ldmatrix.sync.aligned.m8n8.x4.shared.b16 {%0,%1,%2,%3}, [%4];"
        : "=r"(r[0]), "=r"(r[1]), "=r"(r[2]), "=r"(r[3]) : "r"(addr));
}
__device__ __forceinline__ void ldsm_x4_t(uint32_t* r, uint32_t addr) {
    asm volatile("ldmatrix.sync.aligned.m8n8.x4.trans.shared.b16 {%0,%1,%2,%3}, [%4];"
        : "=r"(r[0]), "=r"(r[1]), "=r"(r[2]), "=r"(r[3]) : "r"(addr));
}
// D = A(16x16,f16) * B(16x8,f16) + D   (A row-major, B col-major, f32 accum)
__device__ __forceinline__ void mma_16816(float* c, const uint32_t* a, const uint32_t* b) {
    asm volatile(
        "mma.sync.aligned.m16n8k16.row.col.f32.f16.f16.f32 "
        "{%0,%1,%2,%3}, {%4,%5,%6,%7}, {%8,%9}, {%0,%1,%2,%3};"
        : "+f"(c[0]), "+f"(c[1]), "+f"(c[2]), "+f"(c[3])
        : "r"(a[0]), "r"(a[1]), "r"(a[2]), "r"(a[3]), "r"(b[0]), "r"(b[1]));
}
__device__ __forceinline__ uint32_t pack_h2(float x, float y) {
    __half2 h = __floats2half2_rn(x, y);
    return *(uint32_t*)&h;
}

// ----------------------------- wmma fragment types (GEMM) --------------------
using HFragA  = wmma::fragment<wmma::matrix_a, 16, 16, 16, __half, wmma::row_major>;
using HFragBr = wmma::fragment<wmma::matrix_b, 16, 16, 16, __half, wmma::row_major>;
using HFragC  = wmma::fragment<wmma::accumulator, 16, 16, 16, float>;

// ----------------------------- converts --------------------------------------
__global__ void __launch_bounds__(256)
cvt_kernel(const float* __restrict__ src, __half* __restrict__ dst, int n)
{
    int i = (blockIdx.x * 256 + threadIdx.x) * 8;
    if (i >= n) return;
    float4 a = *(const float4*)(src + i);
    float4 b = *(const float4*)(src + i + 4);
    __half2 h0 = __floats2half2_rn(a.x, a.y);
    __half2 h1 = __floats2half2_rn(a.z, a.w);
    __half2 h2 = __floats2half2_rn(b.x, b.y);
    __half2 h3 = __floats2half2_rn(b.z, b.w);
    uint4 u;
    u.x = *(unsigned*)&h0; u.y = *(unsigned*)&h1;
    u.z = *(unsigned*)&h2; u.w = *(unsigned*)&h3;
    *(uint4*)(dst + i) = u;
}

// ----------------------------- means / gate ----------------------------------
__global__ void __launch_bounds__(256)
mean_kernel(const float* __restrict__ query, const float* __restrict__ memory)
{
    using namespace cfg;
    const int b = blockIdx.y;
    const int d = blockIdx.x * blockDim.x + threadIdx.x;

    const float* qp = query + (size_t)b * T * D + d;
    float s0 = 0.f, s1 = 0.f, s2 = 0.f, s3 = 0.f;
    for (int t = 0; t < T; t += 4) {
        s0 += qp[(size_t)(t + 0) * D];
        s1 += qp[(size_t)(t + 1) * D];
        s2 += qp[(size_t)(t + 2) * D];
        s3 += qp[(size_t)(t + 3) * D];
    }
    g_memin[b * 2 * D + d] = ((s0 + s1) + (s2 + s3)) * (1.0f / T);

    const float* mp = memory + (size_t)b * M * D + d;
    float u0 = 0.f, u1 = 0.f;
    for (int m = 0; m < M; m += 2) {
        u0 += mp[(size_t)(m + 0) * D];
        u1 += mp[(size_t)(m + 1) * D];
    }
    g_memin[b * 2 * D + D + d] = (u0 + u1) * (1.0f / M);
}

__global__ void __launch_bounds__(256)
gate_vals_kernel(const float* __restrict__ Wg, const float* __restrict__ bg)
{
    using namespace cfg;
    const int b = blockIdx.y;
    const int j = blockIdx.x * blockDim.x + threadIdx.x;
    const float* mi = g_memin + b * 2 * D;

    float a0 = 0.f, a1 = 0.f, a2 = 0.f, a3 = 0.f;
    for (int i = 0; i < 2 * D; i += 4) {
        a0 += mi[i + 0] * Wg[(size_t)(i + 0) * D + j];
        a1 += mi[i + 1] * Wg[(size_t)(i + 1) * D + j];
        a2 += mi[i + 2] * Wg[(size_t)(i + 2) * D + j];
        a3 += mi[i + 3] * Wg[(size_t)(i + 3) * D + j];
    }
    float acc = bg[j] + ((a0 + a1) + (a2 + a3));
    g_gatevals[b * D + j] = 1.0f / (1.0f + expf(-acc));
}

__global__ void gate_reduce_kernel()
{
    using namespace cfg;
    __shared__ float red[1024];
    const int t = threadIdx.x;
    red[t] = g_gatevals[t] + g_gatevals[t + 1024] +
             g_gatevals[t + 2048] + g_gatevals[t + 3072];
    __syncthreads();
    for (int s = 512; s > 0; s >>= 1) {
        if (t < s) red[t] += red[t + s];
        __syncthreads();
    }
    if (t == 0) g_scale_val = red[0] * (1.0f / (B * D)) * 0.125f;
}

// ----------------------------- fp16 GEMM (R12, unchanged) --------------------
template <bool HALF_OUT>
__device__ __forceinline__ void gemm_body_h(
    const __half* __restrict__ A, const __half* __restrict__ W,
    const float* __restrict__ bias, __half* __restrict__ Ch,
    float* __restrict__ Cf)
{
    using namespace cfg;
    __shared__ __half As[2][128][40];
    __shared__ __half Bs[2][32][136];
    __shared__ float idxm[256];

    const int tid = threadIdx.x;
    const int warpId = tid >> 5;
    const int wr = warpId >> 2;
    const int wc = warpId & 3;
    const int m0 = blockIdx.y * 128;
    const int n0 = blockIdx.x * 128;

    idxm[tid] = (float)tid;

    auto issue_tile = [&](int k0, int buf) {
#pragma unroll
        for (int t = 0; t < 2; t++) {
            int c = tid + t * 256;
            int r = c >> 2, cc = (c & 3) * 8;
            cp_async16(&As[buf][r][cc], A + (size_t)(m0 + r) * D + k0 + cc);
        }
#pragma unroll
        for (int t = 0; t < 2; t++) {
            int c = tid + t * 256;
            int r = c >> 4, cc = (c & 15) * 8;
            cp_async16(&Bs[buf][r][cc], W + (size_t)(k0 + r) * D + n0 + cc);
        }
        cp_commit();
    };

    HFragC acc[4][2];
#pragma unroll
    for (int i = 0; i < 4; i++)
#pragma unroll
        for (int j = 0; j < 2; j++) wmma::fill_fragment(acc[i][j], 0.f);

    issue_tile(0, 0);
    __syncthreads();
    HFragC idxf;
    wmma::load_matrix_sync(idxf, idxm, 16, wmma::mem_row_major);

    constexpr int NIT = cfg::D / 32;
    for (int kt = 0; kt < NIT; kt++) {
        const int buf = kt & 1;
        if (kt + 1 < NIT) issue_tile((kt + 1) * 32, buf ^ 1);
        if (kt + 1 < NIT) cp_wait<1>(); else cp_wait<0>();
        __syncthreads();

#pragma unroll
        for (int kk = 0; kk < 2; kk++) {
            HFragA af[4];
#pragma unroll
            for (int i = 0; i < 4; i++)
                wmma::load_matrix_sync(af[i], &As[buf][64 * wr + 16 * i][16 * kk], 40);
            HFragBr bf[2];
#pragma unroll
            for (int j = 0; j < 2; j++)
                wmma::load_matrix_sync(bf[j], &Bs[buf][16 * kk][32 * wc + 16 * j], 136);
#pragma unroll
            for (int i = 0; i < 4; i++)
#pragma unroll
                for (int j = 0; j < 2; j++)
                    wmma::mma_sync(acc[i][j], af[i], bf[j], acc[i][j]);
        }
        __syncthreads();
    }

#pragma unroll
    for (int i = 0; i < 4; i++)
#pragma unroll
        for (int j = 0; j < 2; j++) {
            const int rbase = m0 + 64 * wr + 16 * i;
            const int cbase = n0 + 32 * wc + 16 * j;
            if (HALF_OUT) {
#pragma unroll
                for (int e = 0; e < 8; e++) {
                    int v = (int)idxf.x[e];
                    int r = v >> 4, c = v & 15;
                    Ch[(size_t)(rbase + r) * D + cbase + c] =
                        __float2half(acc[i][j].x[e] + __ldg(&bias[cbase + c]));
                }
            } else {
#pragma unroll
                for (int e = 0; e < 8; e++)
                    acc[i][j].x[e] += __ldg(&bias[cbase + ((int)idxf.x[e] & 15)]);
                wmma::store_matrix_sync(Cf + (size_t)rbase * D + cbase,
                                        acc[i][j], D, wmma::mem_row_major);
            }
        }
}

__global__ void __launch_bounds__(256)
gemm_qkv_h_kernel(const float* __restrict__ bq, const float* __restrict__ bk,
                  const float* __restrict__ bv)
{
    const __half *A, *W; const float* bias; __half* C;
    if (blockIdx.z == 0)      { A = g_qh; W = g_Wqh; bias = bq; C = g_Qh; }
    else if (blockIdx.z == 1) { A = g_kh; W = g_Wkh; bias = bk; C = g_Kh; }
    else                      { A = g_vh; W = g_Wvh; bias = bv; C = g_Vh; }
    gemm_body_h<true>(A, W, bias, C, nullptr);
}

__global__ void __launch_bounds__(256)
gemm_out_kernel(const float* __restrict__ bo, float* __restrict__ out)
{
    gemm_body_h<false>(g_Oh, g_Woh, bo, nullptr, out);
}

// ----------------------------- FA2-style flash (raw mma.sync) ----------------
// grid (T/128, H, B), 256 threads = 8 warps; warp w owns rows 16w..16w+15.
// S stays in registers; softmax via quad shuffles; P packed in-register.
__global__ void __launch_bounds__(256)
flash_mma_kernel(float* dummy)
{
    using namespace cfg;
    extern __shared__ __half smh[];
    __half* Qs = smh + QS_OFF;            // [128][LDH]
    __half* Ks = smh + KS_OFF;            // [2][64][LDH]
    __half* Vs = smh + VS_OFF;            // [2][64][LDH]

    const int b = blockIdx.z, h = blockIdx.y, q0 = blockIdx.x * 128;
    const int tid = threadIdx.x;
    const int w = tid >> 5;
    const int lane = tid & 31;
    const float gscale = g_scale_val;

    const __half* Kp = g_Kh + (size_t)b * S * D + h * DH;
    const __half* Vp = g_Vh + (size_t)b * S * D + h * DH;

    // stage Q tile (warp-local rows): warp w writes rows 16w..16w+15
    {
        const int r = tid >> 1, half_ = tid & 1;
        const __half* src = g_Qh + (size_t)(b * T + q0 + r) * D + h * DH + half_ * 32;
        __half* dst = &Qs[r * LDH + half_ * 32];
#pragma unroll
        for (int jj = 0; jj < 4; jj++)
            *(uint4*)(dst + jj * 8) = *(const uint4*)(src + jj * 8);
    }
    __syncwarp();

    // Q A-fragments: qa[kc][0..3] for k-chunks of 16 (DH=64 -> 4 chunks)
    uint32_t qa[4][4];
    {
        const uint32_t qbase = (uint32_t)__cvta_generic_to_shared(Qs);
        const int tr = lane & 15, tc = (lane >> 4) * 8;
#pragma unroll
        for (int kc = 0; kc < 4; kc++)
            ldsm_x4(qa[kc], qbase + (uint32_t)(((16 * w + tr) * LDH + kc * 16 + tc) * 2));
    }

    float of[8][4];
#pragma unroll
    for (int n = 0; n < 8; n++)
#pragma unroll
        for (int e = 0; e < 4; e++) of[n][e] = 0.f;
    float m_lo = -INFINITY, m_hi = -INFINITY, l_lo = 0.f, l_hi = 0.f;

    auto issue_kv = [&](int s0, int buf) {
        __half* kb = Ks + buf * KS_SZ;
        __half* vb = Vs + buf * KS_SZ;
#pragma unroll
        for (int t = 0; t < 2; t++) {
            int c = tid + t * 256;
            int row = c >> 3, col = (c & 7) * 8;
            cp_async16(&kb[row * LDH + col], Kp + (size_t)(s0 + row) * D + col);
        }
#pragma unroll
        for (int t = 0; t < 2; t++) {
            int c = tid + t * 256;
            int row = c >> 3, col = (c & 7) * 8;
            cp_async16(&vb[row * LDH + col], Vp + (size_t)(s0 + row) * D + col);
        }
        cp_commit();
    };

    issue_kv(0, 0);

    const uint32_t ks_base = (uint32_t)__cvta_generic_to_shared(Ks);
    const uint32_t vs_base = (uint32_t)__cvta_generic_to_shared(Vs);
    const int l7 = lane & 7, l3 = lane >> 3;      // ldmatrix lane mapping

    constexpr int NT = cfg::S / 64;               // 32
    for (int it = 0; it < NT; it++) {
        const int buf = it & 1;
        cp_wait<0>();
        __syncthreads();
        if (it + 1 < NT) issue_kv((it + 1) * 64, buf ^ 1);

        const uint32_t kb = ks_base + (uint32_t)(buf * KS_SZ * 2);
        const uint32_t vb = vs_base + (uint32_t)(buf * KS_SZ * 2);

        // ---- S = Q K^T : sc[n] covers keys 8n..8n+7 (m16n8 accum)
        float sc[8][4];
#pragma unroll
        for (int n = 0; n < 8; n++) {
            sc[n][0] = sc[n][1] = sc[n][2] = sc[n][3] = 0.f;
            uint32_t kf[8];
            // non-trans: K tile is [key][dh] == B col-major
            uint32_t rowb = kb + (uint32_t)(((8 * n + l7) * LDH) * 2);
            ldsm_x4(kf,     rowb + (uint32_t)((l3 * 8) * 2));        // dh 0..31
            ldsm_x4(kf + 4, rowb + (uint32_t)((32 + l3 * 8) * 2));   // dh 32..63
#pragma unroll
            for (int kc = 0; kc < 4; kc++)
                mma_16816(sc[n], qa[kc], kf + 2 * kc);
        }

        // ---- register softmax (rows: lo = lane>>2, hi = +8)
        float mx_lo = -INFINITY, mx_hi = -INFINITY;
#pragma unroll
        for (int n = 0; n < 8; n++) {
            sc[n][0] *= gscale; sc[n][1] *= gscale;
            sc[n][2] *= gscale; sc[n][3] *= gscale;
            mx_lo = fmaxf(mx_lo, fmaxf(sc[n][0], sc[n][1]));
            mx_hi = fmaxf(mx_hi, fmaxf(sc[n][2], sc[n][3]));
        }
        mx_lo = fmaxf(mx_lo, __shfl_xor_sync(0xffffffffu, mx_lo, 1));
        mx_lo = fmaxf(mx_lo, __shfl_xor_sync(0xffffffffu, mx_lo, 2));
        mx_hi = fmaxf(mx_hi, __shfl_xor_sync(0xffffffffu, mx_hi, 1));
        mx_hi = fmaxf(mx_hi, __shfl_xor_sync(0xffffffffu, mx_hi, 2));

        const float nm_lo = fmaxf(m_lo, mx_lo);
        const float nm_hi = fmaxf(m_hi, mx_hi);
        const float corr_lo = __expf(m_lo - nm_lo);
        const float corr_hi = __expf(m_hi - nm_hi);
        m_lo = nm_lo; m_hi = nm_hi;

        float sum_lo = 0.f, sum_hi = 0.f;
#pragma unroll
        for (int n = 0; n < 8; n++) {
            sc[n][0] = __expf(sc[n][0] - nm_lo);
            sc[n][1] = __expf(sc[n][1] - nm_lo);
            sc[n][2] = __expf(sc[n][2] - nm_hi);
            sc[n][3] = __expf(sc[n][3] - nm_hi);
            sum_lo += sc[n][0] + sc[n][1];
            sum_hi += sc[n][2] + sc[n][3];
        }
        sum_lo += __shfl_xor_sync(0xffffffffu, sum_lo, 1);
        sum_lo += __shfl_xor_sync(0xffffffffu, sum_lo, 2);
        sum_hi += __shfl_xor_sync(0xffffffffu, sum_hi, 1);
        sum_hi += __shfl_xor_sync(0xffffffffu, sum_hi, 2);
        l_lo = l_lo * corr_lo + sum_lo;
        l_hi = l_hi * corr_hi + sum_hi;

#pragma unroll
        for (int n = 0; n < 8; n++) {
            of[n][0] *= corr_lo; of[n][1] *= corr_lo;
            of[n][2] *= corr_hi; of[n][3] *= corr_hi;
        }

        // ---- pack P into A-fragments (FA2 accum->A layout identity)
        uint32_t pa[4][4];
#pragma unroll
        for (int kc = 0; kc < 4; kc++) {
            pa[kc][0] = pack_h2(sc[2 * kc][0],     sc[2 * kc][1]);
            pa[kc][1] = pack_h2(sc[2 * kc][2],     sc[2 * kc][3]);
            pa[kc][2] = pack_h2(sc[2 * kc + 1][0], sc[2 * kc + 1][1]);
            pa[kc][3] = pack_h2(sc[2 * kc + 1][2], sc[2 * kc + 1][3]);
        }

        // ---- O += P V : of[n] covers dh 8n..8n+7
#pragma unroll
        for (int n = 0; n < 8; n++) {
            uint32_t vf[8];
            // trans: V tile [key][dh] -> B col-major fragments
            uint32_t colb = vb + (uint32_t)((8 * n) * 2);
            ldsm_x4_t(vf,     colb + (uint32_t)(((l3 * 8 + l7) * LDH) * 2));        // keys 0..31
            ldsm_x4_t(vf + 4, colb + (uint32_t)(((32 + l3 * 8 + l7) * LDH) * 2));   // keys 32..63
#pragma unroll
            for (int kc = 0; kc < 4; kc++)
                mma_16816(of[n], pa[kc], vf + 2 * kc);
        }
    }

    // ---- epilogue: normalize rows, store half2
    const float inv_lo = 1.0f / l_lo;
    const float inv_hi = 1.0f / l_hi;
    const int g = lane >> 2, tig = lane & 3;
    __half* orow_lo = g_Oh + (size_t)(b * T + q0 + 16 * w + g) * D + h * DH + tig * 2;
    __half* orow_hi = orow_lo + (size_t)8 * D;
#pragma unroll
    for (int n = 0; n < 8; n++) {
        uint32_t lo = pack_h2(of[n][0] * inv_lo, of[n][1] * inv_lo);
        uint32_t hi = pack_h2(of[n][2] * inv_hi, of[n][3] * inv_hi);
        *(uint32_t*)(orow_lo + 8 * n) = lo;
        *(uint32_t*)(orow_hi + 8 * n) = hi;
    }
    (void)dummy;
}

// ----------------------------- launch ----------------------------------------
extern "C" void kernel_launch(void* const* d_in, const int* in_sizes, int n_in,
                              void* d_out, int out_size)
{
    using namespace cfg;
    (void)in_sizes; (void)n_in; (void)out_size;

    const float* query  = (const float*)d_in[0];
    const float* key    = (const float*)d_in[1];
    const float* value  = (const float*)d_in[2];
    const float* memory = (const float*)d_in[3];
    const float* Wq = (const float*)d_in[4];
    const float* bq = (const float*)d_in[5];
    const float* Wk = (const float*)d_in[6];
    const float* bk = (const float*)d_in[7];
    const float* Wv = (const float*)d_in[8];
    const float* bv = (const float*)d_in[9];
    const float* Wo = (const float*)d_in[10];
    const float* bo = (const float*)d_in[11];
    const float* Wg = (const float*)d_in[12];
    const float* bg = (const float*)d_in[13];
    float* out = (float*)d_out;

    void *qh, *kh, *vh, *wqh, *wkh, *wvh, *woh;
    cudaGetSymbolAddress(&qh,  g_qh);
    cudaGetSymbolAddress(&kh,  g_kh);
    cudaGetSymbolAddress(&vh,  g_vh);
    cudaGetSymbolAddress(&wqh, g_Wqh);
    cudaGetSymbolAddress(&wkh, g_Wkh);
    cudaGetSymbolAddress(&wvh, g_Wvh);
    cudaGetSymbolAddress(&woh, g_Woh);

    cudaFuncSetAttribute(flash_mma_kernel,
                         cudaFuncAttributeMaxDynamicSharedMemorySize, FL_BYTES);

    // gate path (fp32, independent)
    mean_kernel<<<dim3(D / 256, B), 256>>>(query, memory);
    gate_vals_kernel<<<dim3(D / 256, B), 256>>>(Wg, bg);
    gate_reduce_kernel<<<1, 1024>>>();

    // convert inputs + weights to half
    const int nBig = BT * D;
    const int nW   = D * D;
    cvt_kernel<<<nBig / (256 * 8), 256>>>(query, (__half*)qh, nBig);
    cvt_kernel<<<nBig / (256 * 8), 256>>>(key,   (__half*)kh, nBig);
    cvt_kernel<<<nBig / (256 * 8), 256>>>(value, (__half*)vh, nBig);
    cvt_kernel<<<nW / (256 * 8), 256>>>(Wq, (__half*)wqh, nW);
    cvt_kernel<<<nW / (256 * 8), 256>>>(Wk, (__half*)wkh, nW);
    cvt_kernel<<<nW / (256 * 8), 256>>>(Wv, (__half*)wvh, nW);
    cvt_kernel<<<nW / (256 * 8), 256>>>(Wo, (__half*)woh, nW);

    // fused QKV projections (fp16 tensor cores, 64x32 warp tiles)
    gemm_qkv_h_kernel<<<dim3(D / 128, BT / 128, 3), 256>>>(bq, bk, bv);

    // attention (FA2-style mma.sync, register softmax)
    flash_mma_kernel<<<dim3(T / 128, H, B), 256, FL_BYTES>>>(nullptr);

    // output projection -> d_out (fp32 out)
    gemm_out_kernel<<<dim3(D / 128, BT / 128), 256>>>(bo, out);
}

// round 14
// speedup vs baseline: 1.3388x; 1.0202x over previous
#include <cuda_runtime.h>
#include <cuda_fp16.h>
#include <mma.h>
#include <math.h>
#include <stdint.h>

using namespace nvcuda;

// ---------------------------------------------------------------------------
// MemoryGatedAttention  (B=4, T=S=2048, D=1024, H=16, DH=64, M=64)
// Round 14: 3-stage cp.async multistage GEMM (1 barrier/stage) +
// R13's FA2-style flash (register softmax). Single delta vs R13 (866us).
// ---------------------------------------------------------------------------

namespace cfg {
constexpr int B  = 4;
constexpr int T  = 2048;
constexpr int S  = 2048;
constexpr int D  = 1024;
constexpr int H  = 16;
constexpr int DH = 64;
constexpr int M  = 64;
constexpr int BT = B * T;
// flash smem (halves): Qs[128*72] + Ks[2][64*72] + Vs[2][64*72]
constexpr int LDH = 72;
constexpr int QS_OFF = 0;
constexpr int QS_SZ  = 128 * LDH;
constexpr int KS_OFF = QS_SZ;
constexpr int KS_SZ  = 64 * LDH;
constexpr int VS_OFF = KS_OFF + 2 * KS_SZ;
constexpr int FL_BYTES = (VS_OFF + 2 * KS_SZ) * 2;   // 55296 B
// gemm multistage smem (halves)
constexpr int G_STAGES   = 3;
constexpr int GA_STRIDE  = 40;                        // halves
constexpr int GB_STRIDE  = 136;
constexpr int GA_SZ      = 128 * GA_STRIDE;           // 5120
constexpr int GB_SZ      = 32 * GB_STRIDE;            // 4352
constexpr int G_STAGE_SZ = GA_SZ + GB_SZ;             // 9472 halves
constexpr int G_IDX_OFF  = G_STAGES * G_STAGE_SZ;     // halves (even)
constexpr int G_BYTES    = G_IDX_OFF * 2 + 256 * 4;   // 57856 B
}

// ----------------------------- scratch --------------------------------------
__device__ __half g_qh[cfg::BT * cfg::D];
__device__ __half g_kh[cfg::BT * cfg::D];
__device__ __half g_vh[cfg::BT * cfg::D];
__device__ __half g_Wqh[cfg::D * cfg::D];
__device__ __half g_Wkh[cfg::D * cfg::D];
__device__ __half g_Wvh[cfg::D * cfg::D];
__device__ __half g_Woh[cfg::D * cfg::D];
__device__ __half g_Qh[cfg::BT * cfg::D];
__device__ __half g_Kh[cfg::BT * cfg::D];
__device__ __half g_Vh[cfg::BT * cfg::D];
__device__ __half g_Oh[cfg::BT * cfg::D];
__device__ float  g_memin[cfg::B * 2 * cfg::D];
__device__ float  g_gatevals[cfg::B * cfg::D];
__device__ float  g_scale_val;

// ----------------------------- low-level helpers -----------------------------
__device__ __forceinline__ void cp_async16(void* smem_dst, const void* gmem_src) {
    unsigned sa = (unsigned)__cvta_generic_to_shared(smem_dst);
    asm volatile("cp.async.cg.shared.global [%0], [%1], 16;\n" :: "r"(sa), "l"(gmem_src));
}
__device__ __forceinline__ void cp_commit() {
    asm volatile("cp.async.commit_group;\n");
}
template <int N>
__device__ __forceinline__ void cp_wait() {
    asm volatile("cp.async.wait_group %0;\n" :: "n"(N));
}
__device__ __forceinline__ void ldsm_x4(uint32_t* r, uint32_t addr) {
    asm volatile("ldmatrix.sync.aligned.m8n8.x4.shared.b16 {%0,%1,%2,%3}, [%4];"
        : "=r"(r[0]), "=r"(r[1]), "=r"(r[2]), "=r"(r[3]) : "r"(addr));
}
__device__ __forceinline__ void ldsm_x4_t(uint32_t* r, uint32_t addr) {
    asm volatile("ldmatrix.sync.aligned.m8n8.x4.trans.shared.b16 {%0,%1,%2,%3}, [%4];"
        : "=r"(r[0]), "=r"(r[1]), "=r"(r[2]), "=r"(r[3]) : "r"(addr));
}
__device__ __forceinline__ void mma_16816(float* c, const uint32_t* a, const uint32_t* b) {
    asm volatile(
        "mma.sync.aligned.m16n8k16.row.col.f32.f16.f16.f32 "
        "{%0,%1,%2,%3}, {%4,%5,%6,%7}, {%8,%9}, {%0,%1,%2,%3};"
        : "+f"(c[0]), "+f"(c[1]), "+f"(c[2]), "+f"(c[3])
        : "r"(a[0]), "r"(a[1]), "r"(a[2]), "r"(a[3]), "r"(b[0]), "r"(b[1]));
}
__device__ __forceinline__ uint32_t pack_h2(float x, float y) {
    __half2 h = __floats2half2_rn(x, y);
    return *(uint32_t*)&h;
}

using HFragA  = wmma::fragment<wmma::matrix_a, 16, 16, 16, __half, wmma::row_major>;
using HFragBr = wmma::fragment<wmma::matrix_b, 16, 16, 16, __half, wmma::row_major>;
using HFragC  = wmma::fragment<wmma::accumulator, 16, 16, 16, float>;

// ----------------------------- converts --------------------------------------
__global__ void __launch_bounds__(256)
cvt_kernel(const float* __restrict__ src, __half* __restrict__ dst, int n)
{
    int i = (blockIdx.x * 256 + threadIdx.x) * 8;
    if (i >= n) return;
    float4 a = *(const float4*)(src + i);
    float4 b = *(const float4*)(src + i + 4);
    __half2 h0 = __floats2half2_rn(a.x, a.y);
    __half2 h1 = __floats2half2_rn(a.z, a.w);
    __half2 h2 = __floats2half2_rn(b.x, b.y);
    __half2 h3 = __floats2half2_rn(b.z, b.w);
    uint4 u;
    u.x = *(unsigned*)&h0; u.y = *(unsigned*)&h1;
    u.z = *(unsigned*)&h2; u.w = *(unsigned*)&h3;
    *(uint4*)(dst + i) = u;
}

// ----------------------------- means / gate ----------------------------------
__global__ void __launch_bounds__(256)
mean_kernel(const float* __restrict__ query, const float* __restrict__ memory)
{
    using namespace cfg;
    const int b = blockIdx.y;
    const int d = blockIdx.x * blockDim.x + threadIdx.x;

    const float* qp = query + (size_t)b * T * D + d;
    float s0 = 0.f, s1 = 0.f, s2 = 0.f, s3 = 0.f;
    for (int t = 0; t < T; t += 4) {
        s0 += qp[(size_t)(t + 0) * D];
        s1 += qp[(size_t)(t + 1) * D];
        s2 += qp[(size_t)(t + 2) * D];
        s3 += qp[(size_t)(t + 3) * D];
    }
    g_memin[b * 2 * D + d] = ((s0 + s1) + (s2 + s3)) * (1.0f / T);

    const float* mp = memory + (size_t)b * M * D + d;
    float u0 = 0.f, u1 = 0.f;
    for (int m = 0; m < M; m += 2) {
        u0 += mp[(size_t)(m + 0) * D];
        u1 += mp[(size_t)(m + 1) * D];
    }
    g_memin[b * 2 * D + D + d] = (u0 + u1) * (1.0f / M);
}

__global__ void __launch_bounds__(256)
gate_vals_kernel(const float* __restrict__ Wg, const float* __restrict__ bg)
{
    using namespace cfg;
    const int b = blockIdx.y;
    const int j = blockIdx.x * blockDim.x + threadIdx.x;
    const float* mi = g_memin + b * 2 * D;

    float a0 = 0.f, a1 = 0.f, a2 = 0.f, a3 = 0.f;
    for (int i = 0; i < 2 * D; i += 4) {
        a0 += mi[i + 0] * Wg[(size_t)(i + 0) * D + j];
        a1 += mi[i + 1] * Wg[(size_t)(i + 1) * D + j];
        a2 += mi[i + 2] * Wg[(size_t)(i + 2) * D + j];
        a3 += mi[i + 3] * Wg[(size_t)(i + 3) * D + j];
    }
    float acc = bg[j] + ((a0 + a1) + (a2 + a3));
    g_gatevals[b * D + j] = 1.0f / (1.0f + expf(-acc));
}

__global__ void gate_reduce_kernel()
{
    using namespace cfg;
    __shared__ float red[1024];
    const int t = threadIdx.x;
    red[t] = g_gatevals[t] + g_gatevals[t + 1024] +
             g_gatevals[t + 2048] + g_gatevals[t + 3072];
    __syncthreads();
    for (int s = 512; s > 0; s >>= 1) {
        if (t < s) red[t] += red[t + s];
        __syncthreads();
    }
    if (t == 0) g_scale_val = red[0] * (1.0f / (B * D)) * 0.125f;
}

// ----------------------------- fp16 GEMM, 3-stage multistage -----------------
// C = A[8192,1024] @ W[1024,1024] + bias. 128x128 CTA tile, BK=32,
// 8 warps (2x4), warp tile 64x32. ONE __syncthreads per K stage.
template <bool HALF_OUT>
__device__ __forceinline__ void gemm_body_h(
    const __half* __restrict__ A, const __half* __restrict__ W,
    const float* __restrict__ bias, __half* __restrict__ Ch,
    float* __restrict__ Cf)
{
    using namespace cfg;
    extern __shared__ __half gsm[];
    float* idxm = (float*)(gsm + G_IDX_OFF);

    const int tid = threadIdx.x;
    const int warpId = tid >> 5;
    const int wr = warpId >> 2;
    const int wc = warpId & 3;
    const int m0 = blockIdx.y * 128;
    const int n0 = blockIdx.x * 128;

    idxm[tid] = (float)tid;

    auto issue_tile = [&](int kt, int slot) {
        __half* as = gsm + slot * G_STAGE_SZ;
        __half* bs = as + GA_SZ;
        const int k0 = kt * 32;
#pragma unroll
        for (int t = 0; t < 2; t++) {
            int c = tid + t * 256;
            int r = c >> 2, cc = (c & 3) * 8;
            cp_async16(as + r * GA_STRIDE + cc, A + (size_t)(m0 + r) * D + k0 + cc);
        }
#pragma unroll
        for (int t = 0; t < 2; t++) {
            int c = tid + t * 256;
            int r = c >> 4, cc = (c & 15) * 8;
            cp_async16(bs + r * GB_STRIDE + cc, W + (size_t)(k0 + r) * D + n0 + cc);
        }
        cp_commit();
    };

    HFragC acc[4][2];
#pragma unroll
    for (int i = 0; i < 4; i++)
#pragma unroll
        for (int j = 0; j < 2; j++) wmma::fill_fragment(acc[i][j], 0.f);

    issue_tile(0, 0);
    issue_tile(1, 1);
    __syncthreads();                       // idxm visible
    HFragC idxf;
    wmma::load_matrix_sync(idxf, idxm, 16, wmma::mem_row_major);

    constexpr int NIT = cfg::D / 32;       // 32
    int slot = 0;
    for (int kt = 0; kt < NIT; kt++) {
        if (kt + 1 < NIT) cp_wait<1>(); else cp_wait<0>();
        __syncthreads();                   // all warps done reading slot being refilled
        if (kt + 2 < NIT)
            issue_tile(kt + 2, (slot + 2 >= G_STAGES) ? slot + 2 - G_STAGES : slot + 2);

        const __half* as = gsm + slot * G_STAGE_SZ;
        const __half* bs = as + GA_SZ;
#pragma unroll
        for (int kk = 0; kk < 2; kk++) {
            HFragA af[4];
#pragma unroll
            for (int i = 0; i < 4; i++)
                wmma::load_matrix_sync(af[i], as + (64 * wr + 16 * i) * GA_STRIDE + 16 * kk, GA_STRIDE);
            HFragBr bf[2];
#pragma unroll
            for (int j = 0; j < 2; j++)
                wmma::load_matrix_sync(bf[j], bs + (16 * kk) * GB_STRIDE + 32 * wc + 16 * j, GB_STRIDE);
#pragma unroll
            for (int i = 0; i < 4; i++)
#pragma unroll
                for (int j = 0; j < 2; j++)
                    wmma::mma_sync(acc[i][j], af[i], bf[j], acc[i][j]);
        }
        slot = (slot + 1 == G_STAGES) ? 0 : slot + 1;
    }

#pragma unroll
    for (int i = 0; i < 4; i++)
#pragma unroll
        for (int j = 0; j < 2; j++) {
            const int rbase = m0 + 64 * wr + 16 * i;
            const int cbase = n0 + 32 * wc + 16 * j;
            if (HALF_OUT) {
#pragma unroll
                for (int e = 0; e < 8; e++) {
                    int v = (int)idxf.x[e];
                    int r = v >> 4, c = v & 15;
                    Ch[(size_t)(rbase + r) * D + cbase + c] =
                        __float2half(acc[i][j].x[e] + __ldg(&bias[cbase + c]));
                }
            } else {
#pragma unroll
                for (int e = 0; e < 8; e++)
                    acc[i][j].x[e] += __ldg(&bias[cbase + ((int)idxf.x[e] & 15)]);
                wmma::store_matrix_sync(Cf + (size_t)rbase * D + cbase,
                                        acc[i][j], D, wmma::mem_row_major);
            }
        }
}

__global__ void __launch_bounds__(256)
gemm_qkv_h_kernel(const float* __restrict__ bq, const float* __restrict__ bk,
                  const float* __restrict__ bv)
{
    const __half *A, *W; const float* bias; __half* C;
    if (blockIdx.z == 0)      { A = g_qh; W = g_Wqh; bias = bq; C = g_Qh; }
    else if (blockIdx.z == 1) { A = g_kh; W = g_Wkh; bias = bk; C = g_Kh; }
    else                      { A = g_vh; W = g_Wvh; bias = bv; C = g_Vh; }
    gemm_body_h<true>(A, W, bias, C, nullptr);
}

__global__ void __launch_bounds__(256)
gemm_out_kernel(const float* __restrict__ bo, float* __restrict__ out)
{
    gemm_body_h<false>(g_Oh, g_Woh, bo, nullptr, out);
}

// ----------------------------- FA2-style flash (R13, unchanged) --------------
__global__ void __launch_bounds__(256)
flash_mma_kernel(float* dummy)
{
    using namespace cfg;
    extern __shared__ __half smh[];
    __half* Qs = smh + QS_OFF;
    __half* Ks = smh + KS_OFF;
    __half* Vs = smh + VS_OFF;

    const int b = blockIdx.z, h = blockIdx.y, q0 = blockIdx.x * 128;
    const int tid = threadIdx.x;
    const int w = tid >> 5;
    const int lane = tid & 31;
    const float gscale = g_scale_val;

    const __half* Kp = g_Kh + (size_t)b * S * D + h * DH;
    const __half* Vp = g_Vh + (size_t)b * S * D + h * DH;

    {
        const int r = tid >> 1, half_ = tid & 1;
        const __half* src = g_Qh + (size_t)(b * T + q0 + r) * D + h * DH + half_ * 32;
        __half* dst = &Qs[r * LDH + half_ * 32];
#pragma unroll
        for (int jj = 0; jj < 4; jj++)
            *(uint4*)(dst + jj * 8) = *(const uint4*)(src + jj * 8);
    }
    __syncwarp();

    uint32_t qa[4][4];
    {
        const uint32_t qbase = (uint32_t)__cvta_generic_to_shared(Qs);
        const int tr = lane & 15, tc = (lane >> 4) * 8;
#pragma unroll
        for (int kc = 0; kc < 4; kc++)
            ldsm_x4(qa[kc], qbase + (uint32_t)(((16 * w + tr) * LDH + kc * 16 + tc) * 2));
    }

    float of[8][4];
#pragma unroll
    for (int n = 0; n < 8; n++)
#pragma unroll
        for (int e = 0; e < 4; e++) of[n][e] = 0.f;
    float m_lo = -INFINITY, m_hi = -INFINITY, l_lo = 0.f, l_hi = 0.f;

    auto issue_kv = [&](int s0, int buf) {
        __half* kb = Ks + buf * KS_SZ;
        __half* vb = Vs + buf * KS_SZ;
#pragma unroll
        for (int t = 0; t < 2; t++) {
            int c = tid + t * 256;
            int row = c >> 3, col = (c & 7) * 8;
            cp_async16(&kb[row * LDH + col], Kp + (size_t)(s0 + row) * D + col);
        }
#pragma unroll
        for (int t = 0; t < 2; t++) {
            int c = tid + t * 256;
            int row = c >> 3, col = (c & 7) * 8;
            cp_async16(&vb[row * LDH + col], Vp + (size_t)(s0 + row) * D + col);
        }
        cp_commit();
    };

    issue_kv(0, 0);

    const uint32_t ks_base = (uint32_t)__cvta_generic_to_shared(Ks);
    const uint32_t vs_base = (uint32_t)__cvta_generic_to_shared(Vs);
    const int l7 = lane & 7, l3 = lane >> 3;

    constexpr int NT = cfg::S / 64;
    for (int it = 0; it < NT; it++) {
        const int buf = it & 1;
        cp_wait<0>();
        __syncthreads();
        if (it + 1 < NT) issue_kv((it + 1) * 64, buf ^ 1);

        const uint32_t kb = ks_base + (uint32_t)(buf * KS_SZ * 2);
        const uint32_t vb = vs_base + (uint32_t)(buf * KS_SZ * 2);

        float sc[8][4];
#pragma unroll
        for (int n = 0; n < 8; n++) {
            sc[n][0] = sc[n][1] = sc[n][2] = sc[n][3] = 0.f;
            uint32_t kf[8];
            uint32_t rowb = kb + (uint32_t)(((8 * n + l7) * LDH) * 2);
            ldsm_x4(kf,     rowb + (uint32_t)((l3 * 8) * 2));
            ldsm_x4(kf + 4, rowb + (uint32_t)((32 + l3 * 8) * 2));
#pragma unroll
            for (int kc = 0; kc < 4; kc++)
                mma_16816(sc[n], qa[kc], kf + 2 * kc);
        }

        float mx_lo = -INFINITY, mx_hi = -INFINITY;
#pragma unroll
        for (int n = 0; n < 8; n++) {
            sc[n][0] *= gscale; sc[n][1] *= gscale;
            sc[n][2] *= gscale; sc[n][3] *= gscale;
            mx_lo = fmaxf(mx_lo, fmaxf(sc[n][0], sc[n][1]));
            mx_hi = fmaxf(mx_hi, fmaxf(sc[n][2], sc[n][3]));
        }
        mx_lo = fmaxf(mx_lo, __shfl_xor_sync(0xffffffffu, mx_lo, 1));
        mx_lo = fmaxf(mx_lo, __shfl_xor_sync(0xffffffffu, mx_lo, 2));
        mx_hi = fmaxf(mx_hi, __shfl_xor_sync(0xffffffffu, mx_hi, 1));
        mx_hi = fmaxf(mx_hi, __shfl_xor_sync(0xffffffffu, mx_hi, 2));

        const float nm_lo = fmaxf(m_lo, mx_lo);
        const float nm_hi = fmaxf(m_hi, mx_hi);
        const float corr_lo = __expf(m_lo - nm_lo);
        const float corr_hi = __expf(m_hi - nm_hi);
        m_lo = nm_lo; m_hi = nm_hi;

        float sum_lo = 0.f, sum_hi = 0.f;
#pragma unroll
        for (int n = 0; n < 8; n++) {
            sc[n][0] = __expf(sc[n][0] - nm_lo);
            sc[n][1] = __expf(sc[n][1] - nm_lo);
            sc[n][2] = __expf(sc[n][2] - nm_hi);
            sc[n][3] = __expf(sc[n][3] - nm_hi);
            sum_lo += sc[n][0] + sc[n][1];
            sum_hi += sc[n][2] + sc[n][3];
        }
        sum_lo += __shfl_xor_sync(0xffffffffu, sum_lo, 1);
        sum_lo += __shfl_xor_sync(0xffffffffu, sum_lo, 2);
        sum_hi += __shfl_xor_sync(0xffffffffu, sum_hi, 1);
        sum_hi += __shfl_xor_sync(0xffffffffu, sum_hi, 2);
        l_lo = l_lo * corr_lo + sum_lo;
        l_hi = l_hi * corr_hi + sum_hi;

#pragma unroll
        for (int n = 0; n < 8; n++) {
            of[n][0] *= corr_lo; of[n][1] *= corr_lo;
            of[n][2] *= corr_hi; of[n][3] *= corr_hi;
        }

        uint32_t pa[4][4];
#pragma unroll
        for (int kc = 0; kc < 4; kc++) {
            pa[kc][0] = pack_h2(sc[2 * kc][0],     sc[2 * kc][1]);
            pa[kc][1] = pack_h2(sc[2 * kc][2],     sc[2 * kc][3]);
            pa[kc][2] = pack_h2(sc[2 * kc + 1][0], sc[2 * kc + 1][1]);
            pa[kc][3] = pack_h2(sc[2 * kc + 1][2], sc[2 * kc + 1][3]);
        }

#pragma unroll
        for (int n = 0; n < 8; n++) {
            uint32_t vf[8];
            uint32_t colb = vb + (uint32_t)((8 * n) * 2);
            ldsm_x4_t(vf,     colb + (uint32_t)(((l3 * 8 + l7) * LDH) * 2));
            ldsm_x4_t(vf + 4, colb + (uint32_t)(((32 + l3 * 8 + l7) * LDH) * 2));
#pragma unroll
            for (int kc = 0; kc < 4; kc++)
                mma_16816(of[n], pa[kc], vf + 2 * kc);
        }
    }

    const float inv_lo = 1.0f / l_lo;
    const float inv_hi = 1.0f / l_hi;
    const int g = lane >> 2, tig = lane & 3;
    __half* orow_lo = g_Oh + (size_t)(b * T + q0 + 16 * w + g) * D + h * DH + tig * 2;
    __half* orow_hi = orow_lo + (size_t)8 * D;
#pragma unroll
    for (int n = 0; n < 8; n++) {
        uint32_t lo = pack_h2(of[n][0] * inv_lo, of[n][1] * inv_lo);
        uint32_t hi = pack_h2(of[n][2] * inv_hi, of[n][3] * inv_hi);
        *(uint32_t*)(orow_lo + 8 * n) = lo;
        *(uint32_t*)(orow_hi + 8 * n) = hi;
    }
    (void)dummy;
}

// ----------------------------- launch ----------------------------------------
extern "C" void kernel_launch(void* const* d_in, const int* in_sizes, int n_in,
                              void* d_out, int out_size)
{
    using namespace cfg;
    (void)in_sizes; (void)n_in; (void)out_size;

    const float* query  = (const float*)d_in[0];
    const float* key    = (const float*)d_in[1];
    const float* value  = (const float*)d_in[2];
    const float* memory = (const float*)d_in[3];
    const float* Wq = (const float*)d_in[4];
    const float* bq = (const float*)d_in[5];
    const float* Wk = (const float*)d_in[6];
    const float* bk = (const float*)d_in[7];
    const float* Wv = (const float*)d_in[8];
    const float* bv = (const float*)d_in[9];
    const float* Wo = (const float*)d_in[10];
    const float* bo = (const float*)d_in[11];
    const float* Wg = (const float*)d_in[12];
    const float* bg = (const float*)d_in[13];
    float* out = (float*)d_out;

    void *qh, *kh, *vh, *wqh, *wkh, *wvh, *woh;
    cudaGetSymbolAddress(&qh,  g_qh);
    cudaGetSymbolAddress(&kh,  g_kh);
    cudaGetSymbolAddress(&vh,  g_vh);
    cudaGetSymbolAddress(&wqh, g_Wqh);
    cudaGetSymbolAddress(&wkh, g_Wkh);
    cudaGetSymbolAddress(&wvh, g_Wvh);
    cudaGetSymbolAddress(&woh, g_Woh);

    cudaFuncSetAttribute(flash_mma_kernel,
                         cudaFuncAttributeMaxDynamicSharedMemorySize, FL_BYTES);
    cudaFuncSetAttribute(gemm_qkv_h_kernel,
                         cudaFuncAttributeMaxDynamicSharedMemorySize, G_BYTES);
    cudaFuncSetAttribute(gemm_out_kernel,
                         cudaFuncAttributeMaxDynamicSharedMemorySize, G_BYTES);

    // gate path (fp32, independent)
    mean_kernel<<<dim3(D / 256, B), 256>>>(query, memory);
    gate_vals_kernel<<<dim3(D / 256, B), 256>>>(Wg, bg);
    gate_reduce_kernel<<<1, 1024>>>();

    // convert inputs + weights to half
    const int nBig = BT * D;
    const int nW   = D * D;
    cvt_kernel<<<nBig / (256 * 8), 256>>>(query, (__half*)qh, nBig);
    cvt_kernel<<<nBig / (256 * 8), 256>>>(key,   (__half*)kh, nBig);
    cvt_kernel<<<nBig / (256 * 8), 256>>>(value, (__half*)vh, nBig);
    cvt_kernel<<<nW / (256 * 8), 256>>>(Wq, (__half*)wqh, nW);
    cvt_kernel<<<nW / (256 * 8), 256>>>(Wk, (__half*)wkh, nW);
    cvt_kernel<<<nW / (256 * 8), 256>>>(Wv, (__half*)wvh, nW);
    cvt_kernel<<<nW / (256 * 8), 256>>>(Wo, (__half*)woh, nW);

    // fused QKV projections (3-stage multistage fp16 GEMM)
    gemm_qkv_h_kernel<<<dim3(D / 128, BT / 128, 3), 256, G_BYTES>>>(bq, bk, bv);

    // attention (FA2-style mma.sync, register softmax)
    flash_mma_kernel<<<dim3(T / 128, H, B), 256, FL_BYTES>>>(nullptr);

    // output projection -> d_out (fp32 out)
    gemm_out_kernel<<<dim3(D / 128, BT / 128), 256, G_BYTES>>>(bo, out);
}

// round 15
// speedup vs baseline: 1.3459x; 1.0053x over previous
#include <cuda_runtime.h>
#include <cuda_fp16.h>
#include <mma.h>
#include <math.h>
#include <stdint.h>

using namespace nvcuda;

// ---------------------------------------------------------------------------
// MemoryGatedAttention  (B=4, T=S=2048, D=1024, H=16, DH=64, M=64)
// Round 15: GEMM with 128-thread CTAs, 64x64 warp tiles (2x2 warps) --
// 25% less smem traffic, 2 CTA/SM preserved. Flash unchanged from R13/14.
// ---------------------------------------------------------------------------

namespace cfg {
constexpr int B  = 4;
constexpr int T  = 2048;
constexpr int S  = 2048;
constexpr int D  = 1024;
constexpr int H  = 16;
constexpr int DH = 64;
constexpr int M  = 64;
constexpr int BT = B * T;
// flash smem (halves)
constexpr int LDH = 72;
constexpr int QS_OFF = 0;
constexpr int QS_SZ  = 128 * LDH;
constexpr int KS_OFF = QS_SZ;
constexpr int KS_SZ  = 64 * LDH;
constexpr int VS_OFF = KS_OFF + 2 * KS_SZ;
constexpr int FL_BYTES = (VS_OFF + 2 * KS_SZ) * 2;   // 55296 B
// gemm multistage smem (halves)
constexpr int G_STAGES   = 3;
constexpr int GA_STRIDE  = 40;
constexpr int GB_STRIDE  = 136;
constexpr int GA_SZ      = 128 * GA_STRIDE;           // 5120
constexpr int GB_SZ      = 32 * GB_STRIDE;            // 4352
constexpr int G_STAGE_SZ = GA_SZ + GB_SZ;             // 9472 halves
constexpr int G_IDX_OFF  = G_STAGES * G_STAGE_SZ;
constexpr int G_BYTES    = G_IDX_OFF * 2 + 256 * 4;   // 57856 B
}

// ----------------------------- scratch --------------------------------------
__device__ __half g_qh[cfg::BT * cfg::D];
__device__ __half g_kh[cfg::BT * cfg::D];
__device__ __half g_vh[cfg::BT * cfg::D];
__device__ __half g_Wqh[cfg::D * cfg::D];
__device__ __half g_Wkh[cfg::D * cfg::D];
__device__ __half g_Wvh[cfg::D * cfg::D];
__device__ __half g_Woh[cfg::D * cfg::D];
__device__ __half g_Qh[cfg::BT * cfg::D];
__device__ __half g_Kh[cfg::BT * cfg::D];
__device__ __half g_Vh[cfg::BT * cfg::D];
__device__ __half g_Oh[cfg::BT * cfg::D];
__device__ float  g_memin[cfg::B * 2 * cfg::D];
__device__ float  g_gatevals[cfg::B * cfg::D];
__device__ float  g_scale_val;

// ----------------------------- low-level helpers -----------------------------
__device__ __forceinline__ void cp_async16(void* smem_dst, const void* gmem_src) {
    unsigned sa = (unsigned)__cvta_generic_to_shared(smem_dst);
    asm volatile("cp.async.cg.shared.global [%0], [%1], 16;\n" :: "r"(sa), "l"(gmem_src));
}
__device__ __forceinline__ void cp_commit() {
    asm volatile("cp.async.commit_group;\n");
}
template <int N>
__device__ __forceinline__ void cp_wait() {
    asm volatile("cp.async.wait_group %0;\n" :: "n"(N));
}
__device__ __forceinline__ void ldsm_x4(uint32_t* r, uint32_t addr) {
    asm volatile("ldmatrix.sync.aligned.m8n8.x4.shared.b16 {%0,%1,%2,%3}, [%4];"
        : "=r"(r[0]), "=r"(r[1]), "=r"(r[2]), "=r"(r[3]) : "r"(addr));
}
__device__ __forceinline__ void ldsm_x4_t(uint32_t* r, uint32_t addr) {
    asm volatile("ldmatrix.sync.aligned.m8n8.x4.trans.shared.b16 {%0,%1,%2,%3}, [%4];"
        : "=r"(r[0]), "=r"(r[1]), "=r"(r[2]), "=r"(r[3]) : "r"(addr));
}
__device__ __forceinline__ void mma_16816(float* c, const uint32_t* a, const uint32_t* b) {
    asm volatile(
        "mma.sync.aligned.m16n8k16.row.col.f32.f16.f16.f32 "
        "{%0,%1,%2,%3}, {%4,%5,%6,%7}, {%8,%9}, {%0,%1,%2,%3};"
        : "+f"(c[0]), "+f"(c[1]), "+f"(c[2]), "+f"(c[3])
        : "r"(a[0]), "r"(a[1]), "r"(a[2]), "r"(a[3]), "r"(b[0]), "r"(b[1]));
}
__device__ __forceinline__ uint32_t pack_h2(float x, float y) {
    __half2 h = __floats2half2_rn(x, y);
    return *(uint32_t*)&h;
}

using HFragA  = wmma::fragment<wmma::matrix_a, 16, 16, 16, __half, wmma::row_major>;
using HFragBr = wmma::fragment<wmma::matrix_b, 16, 16, 16, __half, wmma::row_major>;
using HFragC  = wmma::fragment<wmma::accumulator, 16, 16, 16, float>;

// ----------------------------- converts --------------------------------------
__global__ void __launch_bounds__(256)
cvt_kernel(const float* __restrict__ src, __half* __restrict__ dst, int n)
{
    int i = (blockIdx.x * 256 + threadIdx.x) * 8;
    if (i >= n) return;
    float4 a = *(const float4*)(src + i);
    float4 b = *(const float4*)(src + i + 4);
    __half2 h0 = __floats2half2_rn(a.x, a.y);
    __half2 h1 = __floats2half2_rn(a.z, a.w);
    __half2 h2 = __floats2half2_rn(b.x, b.y);
    __half2 h3 = __floats2half2_rn(b.z, b.w);
    uint4 u;
    u.x = *(unsigned*)&h0; u.y = *(unsigned*)&h1;
    u.z = *(unsigned*)&h2; u.w = *(unsigned*)&h3;
    *(uint4*)(dst + i) = u;
}

// ----------------------------- means / gate ----------------------------------
__global__ void __launch_bounds__(256)
mean_kernel(const float* __restrict__ query, const float* __restrict__ memory)
{
    using namespace cfg;
    const int b = blockIdx.y;
    const int d = blockIdx.x * blockDim.x + threadIdx.x;

    const float* qp = query + (size_t)b * T * D + d;
    float s0 = 0.f, s1 = 0.f, s2 = 0.f, s3 = 0.f;
    for (int t = 0; t < T; t += 4) {
        s0 += qp[(size_t)(t + 0) * D];
        s1 += qp[(size_t)(t + 1) * D];
        s2 += qp[(size_t)(t + 2) * D];
        s3 += qp[(size_t)(t + 3) * D];
    }
    g_memin[b * 2 * D + d] = ((s0 + s1) + (s2 + s3)) * (1.0f / T);

    const float* mp = memory + (size_t)b * M * D + d;
    float u0 = 0.f, u1 = 0.f;
    for (int m = 0; m < M; m += 2) {
        u0 += mp[(size_t)(m + 0) * D];
        u1 += mp[(size_t)(m + 1) * D];
    }
    g_memin[b * 2 * D + D + d] = (u0 + u1) * (1.0f / M);
}

__global__ void __launch_bounds__(256)
gate_vals_kernel(const float* __restrict__ Wg, const float* __restrict__ bg)
{
    using namespace cfg;
    const int b = blockIdx.y;
    const int j = blockIdx.x * blockDim.x + threadIdx.x;
    const float* mi = g_memin + b * 2 * D;

    float a0 = 0.f, a1 = 0.f, a2 = 0.f, a3 = 0.f;
    for (int i = 0; i < 2 * D; i += 4) {
        a0 += mi[i + 0] * Wg[(size_t)(i + 0) * D + j];
        a1 += mi[i + 1] * Wg[(size_t)(i + 1) * D + j];
        a2 += mi[i + 2] * Wg[(size_t)(i + 2) * D + j];
        a3 += mi[i + 3] * Wg[(size_t)(i + 3) * D + j];
    }
    float acc = bg[j] + ((a0 + a1) + (a2 + a3));
    g_gatevals[b * D + j] = 1.0f / (1.0f + expf(-acc));
}

__global__ void gate_reduce_kernel()
{
    using namespace cfg;
    __shared__ float red[1024];
    const int t = threadIdx.x;
    red[t] = g_gatevals[t] + g_gatevals[t + 1024] +
             g_gatevals[t + 2048] + g_gatevals[t + 3072];
    __syncthreads();
    for (int s = 512; s > 0; s >>= 1) {
        if (t < s) red[t] += red[t + s];
        __syncthreads();
    }
    if (t == 0) g_scale_val = red[0] * (1.0f / (B * D)) * 0.125f;
}

// ----------------------------- fp16 GEMM: 128 thr, 64x64 warp tiles ----------
// C = A[8192,1024] @ W[1024,1024] + bias. CTA tile 128x128, BK=32,
// 4 warps (2x2), warp tile 64x64 = 4x4 wmma fragments. 3-stage, 1 barrier.
template <bool HALF_OUT>
__device__ __forceinline__ void gemm_body_h(
    const __half* __restrict__ A, const __half* __restrict__ W,
    const float* __restrict__ bias, __half* __restrict__ Ch,
    float* __restrict__ Cf)
{
    using namespace cfg;
    extern __shared__ __half gsm[];
    float* idxm = (float*)(gsm + G_IDX_OFF);

    const int tid = threadIdx.x;          // 0..127
    const int warpId = tid >> 5;          // 0..3
    const int wr = warpId >> 1;           // 0..1 -> rows 64*wr
    const int wc = warpId & 1;            // 0..1 -> cols 64*wc
    const int m0 = blockIdx.y * 128;
    const int n0 = blockIdx.x * 128;

    idxm[tid] = (float)tid;
    idxm[tid + 128] = (float)(tid + 128);

    auto issue_tile = [&](int kt, int slot) {
        __half* as = gsm + slot * G_STAGE_SZ;
        __half* bs = as + GA_SZ;
        const int k0 = kt * 32;
#pragma unroll
        for (int t = 0; t < 4; t++) {     // A: 128x32 halves = 512 chunks
            int c = tid + t * 128;
            int r = c >> 2, cc = (c & 3) * 8;
            cp_async16(as + r * GA_STRIDE + cc, A + (size_t)(m0 + r) * D + k0 + cc);
        }
#pragma unroll
        for (int t = 0; t < 4; t++) {     // B: 32x128 halves = 512 chunks
            int c = tid + t * 128;
            int r = c >> 4, cc = (c & 15) * 8;
            cp_async16(bs + r * GB_STRIDE + cc, W + (size_t)(k0 + r) * D + n0 + cc);
        }
        cp_commit();
    };

    HFragC acc[4][4];
#pragma unroll
    for (int i = 0; i < 4; i++)
#pragma unroll
        for (int j = 0; j < 4; j++) wmma::fill_fragment(acc[i][j], 0.f);

    issue_tile(0, 0);
    issue_tile(1, 1);
    __syncthreads();
    HFragC idxf;
    wmma::load_matrix_sync(idxf, idxm, 16, wmma::mem_row_major);

    constexpr int NIT = cfg::D / 32;      // 32
    int slot = 0;
    for (int kt = 0; kt < NIT; kt++) {
        if (kt + 1 < NIT) cp_wait<1>(); else cp_wait<0>();
        __syncthreads();
        if (kt + 2 < NIT)
            issue_tile(kt + 2, (slot + 2 >= G_STAGES) ? slot + 2 - G_STAGES : slot + 2);

        const __half* as = gsm + slot * G_STAGE_SZ;
        const __half* bs = as + GA_SZ;
#pragma unroll
        for (int kk = 0; kk < 2; kk++) {
            HFragA af[4];
#pragma unroll
            for (int i = 0; i < 4; i++)
                wmma::load_matrix_sync(af[i], as + (64 * wr + 16 * i) * GA_STRIDE + 16 * kk, GA_STRIDE);
#pragma unroll
            for (int j = 0; j < 4; j++) {
                HFragBr bf;
                wmma::load_matrix_sync(bf, bs + (16 * kk) * GB_STRIDE + 64 * wc + 16 * j, GB_STRIDE);
#pragma unroll
                for (int i = 0; i < 4; i++)
                    wmma::mma_sync(acc[i][j], af[i], bf, acc[i][j]);
            }
        }
        slot = (slot + 1 == G_STAGES) ? 0 : slot + 1;
    }

#pragma unroll
    for (int i = 0; i < 4; i++)
#pragma unroll
        for (int j = 0; j < 4; j++) {
            const int rbase = m0 + 64 * wr + 16 * i;
            const int cbase = n0 + 64 * wc + 16 * j;
            if (HALF_OUT) {
#pragma unroll
                for (int e = 0; e < 8; e++) {
                    int v = (int)idxf.x[e];
                    int r = v >> 4, c = v & 15;
                    Ch[(size_t)(rbase + r) * D + cbase + c] =
                        __float2half(acc[i][j].x[e] + __ldg(&bias[cbase + c]));
                }
            } else {
#pragma unroll
                for (int e = 0; e < 8; e++)
                    acc[i][j].x[e] += __ldg(&bias[cbase + ((int)idxf.x[e] & 15)]);
                wmma::store_matrix_sync(Cf + (size_t)rbase * D + cbase,
                                        acc[i][j], D, wmma::mem_row_major);
            }
        }
}

__global__ void __launch_bounds__(128)
gemm_qkv_h_kernel(const float* __restrict__ bq, const float* __restrict__ bk,
                  const float* __restrict__ bv)
{
    const __half *A, *W; const float* bias; __half* C;
    if (blockIdx.z == 0)      { A = g_qh; W = g_Wqh; bias = bq; C = g_Qh; }
    else if (blockIdx.z == 1) { A = g_kh; W = g_Wkh; bias = bk; C = g_Kh; }
    else                      { A = g_vh; W = g_Wvh; bias = bv; C = g_Vh; }
    gemm_body_h<true>(A, W, bias, C, nullptr);
}

__global__ void __launch_bounds__(128)
gemm_out_kernel(const float* __restrict__ bo, float* __restrict__ out)
{
    gemm_body_h<false>(g_Oh, g_Woh, bo, nullptr, out);
}

// ----------------------------- FA2-style flash (R13, unchanged) --------------
__global__ void __launch_bounds__(256)
flash_mma_kernel(float* dummy)
{
    using namespace cfg;
    extern __shared__ __half smh[];
    __half* Qs = smh + QS_OFF;
    __half* Ks = smh + KS_OFF;
    __half* Vs = smh + VS_OFF;

    const int b = blockIdx.z, h = blockIdx.y, q0 = blockIdx.x * 128;
    const int tid = threadIdx.x;
    const int w = tid >> 5;
    const int lane = tid & 31;
    const float gscale = g_scale_val;

    const __half* Kp = g_Kh + (size_t)b * S * D + h * DH;
    const __half* Vp = g_Vh + (size_t)b * S * D + h * DH;

    {
        const int r = tid >> 1, half_ = tid & 1;
        const __half* src = g_Qh + (size_t)(b * T + q0 + r) * D + h * DH + half_ * 32;
        __half* dst = &Qs[r * LDH + half_ * 32];
#pragma unroll
        for (int jj = 0; jj < 4; jj++)
            *(uint4*)(dst + jj * 8) = *(const uint4*)(src + jj * 8);
    }
    __syncwarp();

    uint32_t qa[4][4];
    {
        const uint32_t qbase = (uint32_t)__cvta_generic_to_shared(Qs);
        const int tr = lane & 15, tc = (lane >> 4) * 8;
#pragma unroll
        for (int kc = 0; kc < 4; kc++)
            ldsm_x4(qa[kc], qbase + (uint32_t)(((16 * w + tr) * LDH + kc * 16 + tc) * 2));
    }

    float of[8][4];
#pragma unroll
    for (int n = 0; n < 8; n++)
#pragma unroll
        for (int e = 0; e < 4; e++) of[n][e] = 0.f;
    float m_lo = -INFINITY, m_hi = -INFINITY, l_lo = 0.f, l_hi = 0.f;

    auto issue_kv = [&](int s0, int buf) {
        __half* kb = Ks + buf * KS_SZ;
        __half* vb = Vs + buf * KS_SZ;
#pragma unroll
        for (int t = 0; t < 2; t++) {
            int c = tid + t * 256;
            int row = c >> 3, col = (c & 7) * 8;
            cp_async16(&kb[row * LDH + col], Kp + (size_t)(s0 + row) * D + col);
        }
#pragma unroll
        for (int t = 0; t < 2; t++) {
            int c = tid + t * 256;
            int row = c >> 3, col = (c & 7) * 8;
            cp_async16(&vb[row * LDH + col], Vp + (size_t)(s0 + row) * D + col);
        }
        cp_commit();
    };

    issue_kv(0, 0);

    const uint32_t ks_base = (uint32_t)__cvta_generic_to_shared(Ks);
    const uint32_t vs_base = (uint32_t)__cvta_generic_to_shared(Vs);
    const int l7 = lane & 7, l3 = lane >> 3;

    constexpr int NT = cfg::S / 64;
    for (int it = 0; it < NT; it++) {
        const int buf = it & 1;
        cp_wait<0>();
        __syncthreads();
        if (it + 1 < NT) issue_kv((it + 1) * 64, buf ^ 1);

        const uint32_t kb = ks_base + (uint32_t)(buf * KS_SZ * 2);
        const uint32_t vb = vs_base + (uint32_t)(buf * KS_SZ * 2);

        float sc[8][4];
#pragma unroll
        for (int n = 0; n < 8; n++) {
            sc[n][0] = sc[n][1] = sc[n][2] = sc[n][3] = 0.f;
            uint32_t kf[8];
            uint32_t rowb = kb + (uint32_t)(((8 * n + l7) * LDH) * 2);
            ldsm_x4(kf,     rowb + (uint32_t)((l3 * 8) * 2));
            ldsm_x4(kf + 4, rowb + (uint32_t)((32 + l3 * 8) * 2));
#pragma unroll
            for (int kc = 0; kc < 4; kc++)
                mma_16816(sc[n], qa[kc], kf + 2 * kc);
        }

        float mx_lo = -INFINITY, mx_hi = -INFINITY;
#pragma unroll
        for (int n = 0; n < 8; n++) {
            sc[n][0] *= gscale; sc[n][1] *= gscale;
            sc[n][2] *= gscale; sc[n][3] *= gscale;
            mx_lo = fmaxf(mx_lo, fmaxf(sc[n][0], sc[n][1]));
            mx_hi = fmaxf(mx_hi, fmaxf(sc[n][2], sc[n][3]));
        }
        mx_lo = fmaxf(mx_lo, __shfl_xor_sync(0xffffffffu, mx_lo, 1));
        mx_lo = fmaxf(mx_lo, __shfl_xor_sync(0xffffffffu, mx_lo, 2));
        mx_hi = fmaxf(mx_hi, __shfl_xor_sync(0xffffffffu, mx_hi, 1));
        mx_hi = fmaxf(mx_hi, __shfl_xor_sync(0xffffffffu, mx_hi, 2));

        const float nm_lo = fmaxf(m_lo, mx_lo);
        const float nm_hi = fmaxf(m_hi, mx_hi);
        const float corr_lo = __expf(m_lo - nm_lo);
        const float corr_hi = __expf(m_hi - nm_hi);
        m_lo = nm_lo; m_hi = nm_hi;

        float sum_lo = 0.f, sum_hi = 0.f;
#pragma unroll
        for (int n = 0; n < 8; n++) {
            sc[n][0] = __expf(sc[n][0] - nm_lo);
            sc[n][1] = __expf(sc[n][1] - nm_lo);
            sc[n][2] = __expf(sc[n][2] - nm_hi);
            sc[n][3] = __expf(sc[n][3] - nm_hi);
            sum_lo += sc[n][0] + sc[n][1];
            sum_hi += sc[n][2] + sc[n][3];
        }
        sum_lo += __shfl_xor_sync(0xffffffffu, sum_lo, 1);
        sum_lo += __shfl_xor_sync(0xffffffffu, sum_lo, 2);
        sum_hi += __shfl_xor_sync(0xffffffffu, sum_hi, 1);
        sum_hi += __shfl_xor_sync(0xffffffffu, sum_hi, 2);
        l_lo = l_lo * corr_lo + sum_lo;
        l_hi = l_hi * corr_hi + sum_hi;

#pragma unroll
        for (int n = 0; n < 8; n++) {
            of[n][0] *= corr_lo; of[n][1] *= corr_lo;
            of[n][2] *= corr_hi; of[n][3] *= corr_hi;
        }

        uint32_t pa[4][4];
#pragma unroll
        for (int kc = 0; kc < 4; kc++) {
            pa[kc][0] = pack_h2(sc[2 * kc][0],     sc[2 * kc][1]);
            pa[kc][1] = pack_h2(sc[2 * kc][2],     sc[2 * kc][3]);
            pa[kc][2] = pack_h2(sc[2 * kc + 1][0], sc[2 * kc + 1][1]);
            pa[kc][3] = pack_h2(sc[2 * kc + 1][2], sc[2 * kc + 1][3]);
        }

#pragma unroll
        for (int n = 0; n < 8; n++) {
            uint32_t vf[8];
            uint32_t colb = vb + (uint32_t)((8 * n) * 2);
            ldsm_x4_t(vf,     colb + (uint32_t)(((l3 * 8 + l7) * LDH) * 2));
            ldsm_x4_t(vf + 4, colb + (uint32_t)(((32 + l3 * 8 + l7) * LDH) * 2));
#pragma unroll
            for (int kc = 0; kc < 4; kc++)
                mma_16816(of[n], pa[kc], vf + 2 * kc);
        }
    }

    const float inv_lo = 1.0f / l_lo;
    const float inv_hi = 1.0f / l_hi;
    const int g = lane >> 2, tig = lane & 3;
    __half* orow_lo = g_Oh + (size_t)(b * T + q0 + 16 * w + g) * D + h * DH + tig * 2;
    __half* orow_hi = orow_lo + (size_t)8 * D;
#pragma unroll
    for (int n = 0; n < 8; n++) {
        uint32_t lo = pack_h2(of[n][0] * inv_lo, of[n][1] * inv_lo);
        uint32_t hi = pack_h2(of[n][2] * inv_hi, of[n][3] * inv_hi);
        *(uint32_t*)(orow_lo + 8 * n) = lo;
        *(uint32_t*)(orow_hi + 8 * n) = hi;
    }
    (void)dummy;
}

// ----------------------------- launch ----------------------------------------
extern "C" void kernel_launch(void* const* d_in, const int* in_sizes, int n_in,
                              void* d_out, int out_size)
{
    using namespace cfg;
    (void)in_sizes; (void)n_in; (void)out_size;

    const float* query  = (const float*)d_in[0];
    const float* key    = (const float*)d_in[1];
    const float* value  = (const float*)d_in[2];
    const float* memory = (const float*)d_in[3];
    const float* Wq = (const float*)d_in[4];
    const float* bq = (const float*)d_in[5];
    const float* Wk = (const float*)d_in[6];
    const float* bk = (const float*)d_in[7];
    const float* Wv = (const float*)d_in[8];
    const float* bv = (const float*)d_in[9];
    const float* Wo = (const float*)d_in[10];
    const float* bo = (const float*)d_in[11];
    const float* Wg = (const float*)d_in[12];
    const float* bg = (const float*)d_in[13];
    float* out = (float*)d_out;

    void *qh, *kh, *vh, *wqh, *wkh, *wvh, *woh;
    cudaGetSymbolAddress(&qh,  g_qh);
    cudaGetSymbolAddress(&kh,  g_kh);
    cudaGetSymbolAddress(&vh,  g_vh);
    cudaGetSymbolAddress(&wqh, g_Wqh);
    cudaGetSymbolAddress(&wkh, g_Wkh);
    cudaGetSymbolAddress(&wvh, g_Wvh);
    cudaGetSymbolAddress(&woh, g_Woh);

    cudaFuncSetAttribute(flash_mma_kernel,
                         cudaFuncAttributeMaxDynamicSharedMemorySize, FL_BYTES);
    cudaFuncSetAttribute(gemm_qkv_h_kernel,
                         cudaFuncAttributeMaxDynamicSharedMemorySize, G_BYTES);
    cudaFuncSetAttribute(gemm_out_kernel,
                         cudaFuncAttributeMaxDynamicSharedMemorySize, G_BYTES);

    // gate path (fp32, independent)
    mean_kernel<<<dim3(D / 256, B), 256>>>(query, memory);
    gate_vals_kernel<<<dim3(D / 256, B), 256>>>(Wg, bg);
    gate_reduce_kernel<<<1, 1024>>>();

    // convert inputs + weights to half
    const int nBig = BT * D;
    const int nW   = D * D;
    cvt_kernel<<<nBig / (256 * 8), 256>>>(query, (__half*)qh, nBig);
    cvt_kernel<<<nBig / (256 * 8), 256>>>(key,   (__half*)kh, nBig);
    cvt_kernel<<<nBig / (256 * 8), 256>>>(value, (__half*)vh, nBig);
    cvt_kernel<<<nW / (256 * 8), 256>>>(Wq, (__half*)wqh, nW);
    cvt_kernel<<<nW / (256 * 8), 256>>>(Wk, (__half*)wkh, nW);
    cvt_kernel<<<nW / (256 * 8), 256>>>(Wv, (__half*)wvh, nW);
    cvt_kernel<<<nW / (256 * 8), 256>>>(Wo, (__half*)woh, nW);

    // fused QKV projections (128-thr, 64x64 warp tiles)
    gemm_qkv_h_kernel<<<dim3(D / 128, BT / 128, 3), 128, G_BYTES>>>(bq, bk, bv);

    // attention (FA2-style mma.sync, register softmax)
    flash_mma_kernel<<<dim3(T / 128, H, B), 256, FL_BYTES>>>(nullptr);

    // output projection -> d_out (fp32 out)
    gemm_out_kernel<<<dim3(D / 128, BT / 128), 128, G_BYTES>>>(bo, out);
}

// round 17
// speedup vs baseline: 1.3689x; 1.0171x over previous
#include <cuda_runtime.h>
#include <cuda_fp16.h>
#include <mma.h>
#include <math.h>
#include <stdint.h>

using namespace nvcuda;

// ---------------------------------------------------------------------------
// MemoryGatedAttention  (B=4, T=S=2048, D=1024, H=16, DH=64, M=64)
// Round 17 (re-bench of R16 after infra failure): flash with 128-key K/V
// tiles (half the per-key softmax overhead). GEMMs identical to R15 (844.7us).
// ---------------------------------------------------------------------------

namespace cfg {
constexpr int B  = 4;
constexpr int T  = 2048;
constexpr int S  = 2048;
constexpr int D  = 1024;
constexpr int H  = 16;
constexpr int DH = 64;
constexpr int M  = 64;
constexpr int BT = B * T;
// flash smem (halves): Qs[128*72] + Ks[2][128*72] + Vs[2][128*72]
constexpr int LDH = 72;
constexpr int QS_OFF = 0;
constexpr int QS_SZ  = 128 * LDH;              // 9216
constexpr int KS_OFF = QS_SZ;
constexpr int KS_SZ  = 128 * LDH;              // 9216 per buffer
constexpr int VS_OFF = KS_OFF + 2 * KS_SZ;
constexpr int FL_BYTES = (VS_OFF + 2 * KS_SZ) * 2;   // 92160 B
// gemm multistage smem (halves)
constexpr int G_STAGES   = 3;
constexpr int GA_STRIDE  = 40;
constexpr int GB_STRIDE  = 136;
constexpr int GA_SZ      = 128 * GA_STRIDE;
constexpr int GB_SZ      = 32 * GB_STRIDE;
constexpr int G_STAGE_SZ = GA_SZ + GB_SZ;
constexpr int G_IDX_OFF  = G_STAGES * G_STAGE_SZ;
constexpr int G_BYTES    = G_IDX_OFF * 2 + 256 * 4;   // 57856 B
}

// ----------------------------- scratch --------------------------------------
__device__ __half g_qh[cfg::BT * cfg::D];
__device__ __half g_kh[cfg::BT * cfg::D];
__device__ __half g_vh[cfg::BT * cfg::D];
__device__ __half g_Wqh[cfg::D * cfg::D];
__device__ __half g_Wkh[cfg::D * cfg::D];
__device__ __half g_Wvh[cfg::D * cfg::D];
__device__ __half g_Woh[cfg::D * cfg::D];
__device__ __half g_Qh[cfg::BT * cfg::D];
__device__ __half g_Kh[cfg::BT * cfg::D];
__device__ __half g_Vh[cfg::BT * cfg::D];
__device__ __half g_Oh[cfg::BT * cfg::D];
__device__ float  g_memin[cfg::B * 2 * cfg::D];
__device__ float  g_gatevals[cfg::B * cfg::D];
__device__ float  g_scale_val;

// ----------------------------- low-level helpers -----------------------------
__device__ __forceinline__ void cp_async16(void* smem_dst, const void* gmem_src) {
    unsigned sa = (unsigned)__cvta_generic_to_shared(smem_dst);
    asm volatile("cp.async.cg.shared.global [%0], [%1], 16;\n" :: "r"(sa), "l"(gmem_src));
}
__device__ __forceinline__ void cp_commit() {
    asm volatile("cp.async.commit_group;\n");
}
template <int N>
__device__ __forceinline__ void cp_wait() {
    asm volatile("cp.async.wait_group %0;\n" :: "n"(N));
}
__device__ __forceinline__ void ldsm_x4(uint32_t* r, uint32_t addr) {
    asm volatile("ldmatrix.sync.aligned.m8n8.x4.shared.b16 {%0,%1,%2,%3}, [%4];"
        : "=r"(r[0]), "=r"(r[1]), "=r"(r[2]), "=r"(r[3]) : "r"(addr));
}
__device__ __forceinline__ void ldsm_x4_t(uint32_t* r, uint32_t addr) {
    asm volatile("ldmatrix.sync.aligned.m8n8.x4.trans.shared.b16 {%0,%1,%2,%3}, [%4];"
        : "=r"(r[0]), "=r"(r[1]), "=r"(r[2]), "=r"(r[3]) : "r"(addr));
}
__device__ __forceinline__ void mma_16816(float* c, const uint32_t* a, const uint32_t* b) {
    asm volatile(
        "mma.sync.aligned.m16n8k16.row.col.f32.f16.f16.f32 "
        "{%0,%1,%2,%3}, {%4,%5,%6,%7}, {%8,%9}, {%0,%1,%2,%3};"
        : "+f"(c[0]), "+f"(c[1]), "+f"(c[2]), "+f"(c[3])
        : "r"(a[0]), "r"(a[1]), "r"(a[2]), "r"(a[3]), "r"(b[0]), "r"(b[1]));
}
__device__ __forceinline__ uint32_t pack_h2(float x, float y) {
    __half2 h = __floats2half2_rn(x, y);
    return *(uint32_t*)&h;
}

using HFragA  = wmma::fragment<wmma::matrix_a, 16, 16, 16, __half, wmma::row_major>;
using HFragBr = wmma::fragment<wmma::matrix_b, 16, 16, 16, __half, wmma::row_major>;
using HFragC  = wmma::fragment<wmma::accumulator, 16, 16, 16, float>;

// ----------------------------- converts --------------------------------------
__global__ void __launch_bounds__(256)
cvt_kernel(const float* __restrict__ src, __half* __restrict__ dst, int n)
{
    int i = (blockIdx.x * 256 + threadIdx.x) * 8;
    if (i >= n) return;
    float4 a = *(const float4*)(src + i);
    float4 b = *(const float4*)(src + i + 4);
    __half2 h0 = __floats2half2_rn(a.x, a.y);
    __half2 h1 = __floats2half2_rn(a.z, a.w);
    __half2 h2 = __floats2half2_rn(b.x, b.y);
    __half2 h3 = __floats2half2_rn(b.z, b.w);
    uint4 u;
    u.x = *(unsigned*)&h0; u.y = *(unsigned*)&h1;
    u.z = *(unsigned*)&h2; u.w = *(unsigned*)&h3;
    *(uint4*)(dst + i) = u;
}

// ----------------------------- means / gate ----------------------------------
__global__ void __launch_bounds__(256)
mean_kernel(const float* __restrict__ query, const float* __restrict__ memory)
{
    using namespace cfg;
    const int b = blockIdx.y;
    const int d = blockIdx.x * blockDim.x + threadIdx.x;

    const float* qp = query + (size_t)b * T * D + d;
    float s0 = 0.f, s1 = 0.f, s2 = 0.f, s3 = 0.f;
    for (int t = 0; t < T; t += 4) {
        s0 += qp[(size_t)(t + 0) * D];
        s1 += qp[(size_t)(t + 1) * D];
        s2 += qp[(size_t)(t + 2) * D];
        s3 += qp[(size_t)(t + 3) * D];
    }
    g_memin[b * 2 * D + d] = ((s0 + s1) + (s2 + s3)) * (1.0f / T);

    const float* mp = memory + (size_t)b * M * D + d;
    float u0 = 0.f, u1 = 0.f;
    for (int m = 0; m < M; m += 2) {
        u0 += mp[(size_t)(m + 0) * D];
        u1 += mp[(size_t)(m + 1) * D];
    }
    g_memin[b * 2 * D + D + d] = (u0 + u1) * (1.0f / M);
}

__global__ void __launch_bounds__(256)
gate_vals_kernel(const float* __restrict__ Wg, const float* __restrict__ bg)
{
    using namespace cfg;
    const int b = blockIdx.y;
    const int j = blockIdx.x * blockDim.x + threadIdx.x;
    const float* mi = g_memin + b * 2 * D;

    float a0 = 0.f, a1 = 0.f, a2 = 0.f, a3 = 0.f;
    for (int i = 0; i < 2 * D; i += 4) {
        a0 += mi[i + 0] * Wg[(size_t)(i + 0) * D + j];
        a1 += mi[i + 1] * Wg[(size_t)(i + 1) * D + j];
        a2 += mi[i + 2] * Wg[(size_t)(i + 2) * D + j];
        a3 += mi[i + 3] * Wg[(size_t)(i + 3) * D + j];
    }
    float acc = bg[j] + ((a0 + a1) + (a2 + a3));
    g_gatevals[b * D + j] = 1.0f / (1.0f + expf(-acc));
}

__global__ void gate_reduce_kernel()
{
    using namespace cfg;
    __shared__ float red[1024];
    const int t = threadIdx.x;
    red[t] = g_gatevals[t] + g_gatevals[t + 1024] +
             g_gatevals[t + 2048] + g_gatevals[t + 3072];
    __syncthreads();
    for (int s = 512; s > 0; s >>= 1) {
        if (t < s) red[t] += red[t + s];
        __syncthreads();
    }
    if (t == 0) g_scale_val = red[0] * (1.0f / (B * D)) * 0.125f;
}

// ----------------------------- fp16 GEMM (R15, unchanged) --------------------
template <bool HALF_OUT>
__device__ __forceinline__ void gemm_body_h(
    const __half* __restrict__ A, const __half* __restrict__ W,
    const float* __restrict__ bias, __half* __restrict__ Ch,
    float* __restrict__ Cf)
{
    using namespace cfg;
    extern __shared__ __half gsm[];
    float* idxm = (float*)(gsm + G_IDX_OFF);

    const int tid = threadIdx.x;          // 0..127
    const int warpId = tid >> 5;
    const int wr = warpId >> 1;
    const int wc = warpId & 1;
    const int m0 = blockIdx.y * 128;
    const int n0 = blockIdx.x * 128;

    idxm[tid] = (float)tid;
    idxm[tid + 128] = (float)(tid + 128);

    auto issue_tile = [&](int kt, int slot) {
        __half* as = gsm + slot * G_STAGE_SZ;
        __half* bs = as + GA_SZ;
        const int k0 = kt * 32;
#pragma unroll
        for (int t = 0; t < 4; t++) {
            int c = tid + t * 128;
            int r = c >> 2, cc = (c & 3) * 8;
            cp_async16(as + r * GA_STRIDE + cc, A + (size_t)(m0 + r) * D + k0 + cc);
        }
#pragma unroll
        for (int t = 0; t < 4; t++) {
            int c = tid + t * 128;
            int r = c >> 4, cc = (c & 15) * 8;
            cp_async16(bs + r * GB_STRIDE + cc, W + (size_t)(k0 + r) * D + n0 + cc);
        }
        cp_commit();
    };

    HFragC acc[4][4];
#pragma unroll
    for (int i = 0; i < 4; i++)
#pragma unroll
        for (int j = 0; j < 4; j++) wmma::fill_fragment(acc[i][j], 0.f);

    issue_tile(0, 0);
    issue_tile(1, 1);
    __syncthreads();
    HFragC idxf;
    wmma::load_matrix_sync(idxf, idxm, 16, wmma::mem_row_major);

    constexpr int NIT = cfg::D / 32;
    int slot = 0;
    for (int kt = 0; kt < NIT; kt++) {
        if (kt + 1 < NIT) cp_wait<1>(); else cp_wait<0>();
        __syncthreads();
        if (kt + 2 < NIT)
            issue_tile(kt + 2, (slot + 2 >= G_STAGES) ? slot + 2 - G_STAGES : slot + 2);

        const __half* as = gsm + slot * G_STAGE_SZ;
        const __half* bs = as + GA_SZ;
#pragma unroll
        for (int kk = 0; kk < 2; kk++) {
            HFragA af[4];
#pragma unroll
            for (int i = 0; i < 4; i++)
                wmma::load_matrix_sync(af[i], as + (64 * wr + 16 * i) * GA_STRIDE + 16 * kk, GA_STRIDE);
#pragma unroll
            for (int j = 0; j < 4; j++) {
                HFragBr bf;
                wmma::load_matrix_sync(bf, bs + (16 * kk) * GB_STRIDE + 64 * wc + 16 * j, GB_STRIDE);
#pragma unroll
                for (int i = 0; i < 4; i++)
                    wmma::mma_sync(acc[i][j], af[i], bf, acc[i][j]);
            }
        }
        slot = (slot + 1 == G_STAGES) ? 0 : slot + 1;
    }

#pragma unroll
    for (int i = 0; i < 4; i++)
#pragma unroll
        for (int j = 0; j < 4; j++) {
            const int rbase = m0 + 64 * wr + 16 * i;
            const int cbase = n0 + 64 * wc + 16 * j;
            if (HALF_OUT) {
#pragma unroll
                for (int e = 0; e < 8; e++) {
                    int v = (int)idxf.x[e];
                    int r = v >> 4, c = v & 15;
                    Ch[(size_t)(rbase + r) * D + cbase + c] =
                        __float2half(acc[i][j].x[e] + __ldg(&bias[cbase + c]));
                }
            } else {
#pragma unroll
                for (int e = 0; e < 8; e++)
                    acc[i][j].x[e] += __ldg(&bias[cbase + ((int)idxf.x[e] & 15)]);
                wmma::store_matrix_sync(Cf + (size_t)rbase * D + cbase,
                                        acc[i][j], D, wmma::mem_row_major);
            }
        }
}

__global__ void __launch_bounds__(128)
gemm_qkv_h_kernel(const float* __restrict__ bq, const float* __restrict__ bk,
                  const float* __restrict__ bv)
{
    const __half *A, *W; const float* bias; __half* C;
    if (blockIdx.z == 0)      { A = g_qh; W = g_Wqh; bias = bq; C = g_Qh; }
    else if (blockIdx.z == 1) { A = g_kh; W = g_Wkh; bias = bk; C = g_Kh; }
    else                      { A = g_vh; W = g_Wvh; bias = bv; C = g_Vh; }
    gemm_body_h<true>(A, W, bias, C, nullptr);
}

__global__ void __launch_bounds__(128)
gemm_out_kernel(const float* __restrict__ bo, float* __restrict__ out)
{
    gemm_body_h<false>(g_Oh, g_Woh, bo, nullptr, out);
}

// ----------------------------- FA2-style flash, 128-key tiles ----------------
// grid (T/128, H, B), 256 threads = 8 warps; warp w owns rows 16w..16w+15.
__global__ void __launch_bounds__(256)
flash_mma_kernel(float* dummy)
{
    using namespace cfg;
    extern __shared__ __half smh[];
    __half* Qs = smh + QS_OFF;
    __half* Ks = smh + KS_OFF;            // [2][128][LDH]
    __half* Vs = smh + VS_OFF;            // [2][128][LDH]

    const int b = blockIdx.z, h = blockIdx.y, q0 = blockIdx.x * 128;
    const int tid = threadIdx.x;
    const int w = tid >> 5;
    const int lane = tid & 31;
    const float gscale = g_scale_val;

    const __half* Kp = g_Kh + (size_t)b * S * D + h * DH;
    const __half* Vp = g_Vh + (size_t)b * S * D + h * DH;

    // stage Q tile (warp-local rows)
    {
        const int r = tid >> 1, half_ = tid & 1;
        const __half* src = g_Qh + (size_t)(b * T + q0 + r) * D + h * DH + half_ * 32;
        __half* dst = &Qs[r * LDH + half_ * 32];
#pragma unroll
        for (int jj = 0; jj < 4; jj++)
            *(uint4*)(dst + jj * 8) = *(const uint4*)(src + jj * 8);
    }
    __syncwarp();

    uint32_t qa[4][4];
    {
        const uint32_t qbase = (uint32_t)__cvta_generic_to_shared(Qs);
        const int tr = lane & 15, tc = (lane >> 4) * 8;
#pragma unroll
        for (int kc = 0; kc < 4; kc++)
            ldsm_x4(qa[kc], qbase + (uint32_t)(((16 * w + tr) * LDH + kc * 16 + tc) * 2));
    }

    float of[8][4];
#pragma unroll
    for (int n = 0; n < 8; n++)
#pragma unroll
        for (int e = 0; e < 4; e++) of[n][e] = 0.f;
    float m_lo = -INFINITY, m_hi = -INFINITY, l_lo = 0.f, l_hi = 0.f;

    // K/V tile loader: 128 rows x 64 halves each -> 4 chunks/thread/array
    auto issue_kv = [&](int s0, int buf) {
        __half* kb = Ks + buf * KS_SZ;
        __half* vb = Vs + buf * KS_SZ;
#pragma unroll
        for (int t = 0; t < 4; t++) {
            int c = tid + t * 256;                    // 0..1023
            int row = c >> 3, col = (c & 7) * 8;
            cp_async16(&kb[row * LDH + col], Kp + (size_t)(s0 + row) * D + col);
        }
#pragma unroll
        for (int t = 0; t < 4; t++) {
            int c = tid + t * 256;
            int row = c >> 3, col = (c & 7) * 8;
            cp_async16(&vb[row * LDH + col], Vp + (size_t)(s0 + row) * D + col);
        }
        cp_commit();
    };

    issue_kv(0, 0);

    const uint32_t ks_base = (uint32_t)__cvta_generic_to_shared(Ks);
    const uint32_t vs_base = (uint32_t)__cvta_generic_to_shared(Vs);
    const int l7 = lane & 7, l3 = lane >> 3;

    constexpr int NT = cfg::S / 128;              // 16 tiles
    for (int it = 0; it < NT; it++) {
        const int buf = it & 1;
        cp_wait<0>();
        __syncthreads();
        if (it + 1 < NT) issue_kv((it + 1) * 128, buf ^ 1);

        const uint32_t kb = ks_base + (uint32_t)(buf * KS_SZ * 2);
        const uint32_t vb = vs_base + (uint32_t)(buf * KS_SZ * 2);

        // ---- S = Q K^T : sc[n] covers keys 8n..8n+7, n = 0..15
        float sc[16][4];
#pragma unroll
        for (int n = 0; n < 16; n++) {
            sc[n][0] = sc[n][1] = sc[n][2] = sc[n][3] = 0.f;
            uint32_t kf[8];
            uint32_t rowb = kb + (uint32_t)(((8 * n + l7) * LDH) * 2);
            ldsm_x4(kf,     rowb + (uint32_t)((l3 * 8) * 2));
            ldsm_x4(kf + 4, rowb + (uint32_t)((32 + l3 * 8) * 2));
#pragma unroll
            for (int kc = 0; kc < 4; kc++)
                mma_16816(sc[n], qa[kc], kf + 2 * kc);
        }

        // ---- register softmax
        float mx_lo = -INFINITY, mx_hi = -INFINITY;
#pragma unroll
        for (int n = 0; n < 16; n++) {
            sc[n][0] *= gscale; sc[n][1] *= gscale;
            sc[n][2] *= gscale; sc[n][3] *= gscale;
            mx_lo = fmaxf(mx_lo, fmaxf(sc[n][0], sc[n][1]));
            mx_hi = fmaxf(mx_hi, fmaxf(sc[n][2], sc[n][3]));
        }
        mx_lo = fmaxf(mx_lo, __shfl_xor_sync(0xffffffffu, mx_lo, 1));
        mx_lo = fmaxf(mx_lo, __shfl_xor_sync(0xffffffffu, mx_lo, 2));
        mx_hi = fmaxf(mx_hi, __shfl_xor_sync(0xffffffffu, mx_hi, 1));
        mx_hi = fmaxf(mx_hi, __shfl_xor_sync(0xffffffffu, mx_hi, 2));

        const float nm_lo = fmaxf(m_lo, mx_lo);
        const float nm_hi = fmaxf(m_hi, mx_hi);
        const float corr_lo = __expf(m_lo - nm_lo);
        const float corr_hi = __expf(m_hi - nm_hi);
        m_lo = nm_lo; m_hi = nm_hi;

        float sum_lo = 0.f, sum_hi = 0.f;
#pragma unroll
        for (int n = 0; n < 16; n++) {
            sc[n][0] = __expf(sc[n][0] - nm_lo);
            sc[n][1] = __expf(sc[n][1] - nm_lo);
            sc[n][2] = __expf(sc[n][2] - nm_hi);
            sc[n][3] = __expf(sc[n][3] - nm_hi);
            sum_lo += sc[n][0] + sc[n][1];
            sum_hi += sc[n][2] + sc[n][3];
        }
        sum_lo += __shfl_xor_sync(0xffffffffu, sum_lo, 1);
        sum_lo += __shfl_xor_sync(0xffffffffu, sum_lo, 2);
        sum_hi += __shfl_xor_sync(0xffffffffu, sum_hi, 1);
        sum_hi += __shfl_xor_sync(0xffffffffu, sum_hi, 2);
        l_lo = l_lo * corr_lo + sum_lo;
        l_hi = l_hi * corr_hi + sum_hi;

#pragma unroll
        for (int n = 0; n < 8; n++) {
            of[n][0] *= corr_lo; of[n][1] *= corr_lo;
            of[n][2] *= corr_hi; of[n][3] *= corr_hi;
        }

        // ---- pack P into A-fragments: pa[kc] covers keys 16kc..16kc+15
        uint32_t pa[8][4];
#pragma unroll
        for (int kc = 0; kc < 8; kc++) {
            pa[kc][0] = pack_h2(sc[2 * kc][0],     sc[2 * kc][1]);
            pa[kc][1] = pack_h2(sc[2 * kc][2],     sc[2 * kc][3]);
            pa[kc][2] = pack_h2(sc[2 * kc + 1][0], sc[2 * kc + 1][1]);
            pa[kc][3] = pack_h2(sc[2 * kc + 1][2], sc[2 * kc + 1][3]);
        }

        // ---- O += P V : of[n] covers dh 8n..8n+7
#pragma unroll
        for (int n = 0; n < 8; n++) {
            uint32_t vf[16];
            uint32_t colb = vb + (uint32_t)((8 * n) * 2);
#pragma unroll
            for (int gq = 0; gq < 4; gq++)
                ldsm_x4_t(vf + 4 * gq,
                          colb + (uint32_t)(((32 * gq + l3 * 8 + l7) * LDH) * 2));
#pragma unroll
            for (int kc = 0; kc < 8; kc++)
                mma_16816(of[n], pa[kc], vf + 2 * kc);
        }
    }

    // ---- epilogue
    const float inv_lo = 1.0f / l_lo;
    const float inv_hi = 1.0f / l_hi;
    const int g = lane >> 2, tig = lane & 3;
    __half* orow_lo = g_Oh + (size_t)(b * T + q0 + 16 * w + g) * D + h * DH + tig * 2;
    __half* orow_hi = orow_lo + (size_t)8 * D;
#pragma unroll
    for (int n = 0; n < 8; n++) {
        uint32_t lo = pack_h2(of[n][0] * inv_lo, of[n][1] * inv_lo);
        uint32_t hi = pack_h2(of[n][2] * inv_hi, of[n][3] * inv_hi);
        *(uint32_t*)(orow_lo + 8 * n) = lo;
        *(uint32_t*)(orow_hi + 8 * n) = hi;
    }
    (void)dummy;
}

// ----------------------------- launch ----------------------------------------
extern "C" void kernel_launch(void* const* d_in, const int* in_sizes, int n_in,
                              void* d_out, int out_size)
{
    using namespace cfg;
    (void)in_sizes; (void)n_in; (void)out_size;

    const float* query  = (const float*)d_in[0];
    const float* key    = (const float*)d_in[1];
    const float* value  = (const float*)d_in[2];
    const float* memory = (const float*)d_in[3];
    const float* Wq = (const float*)d_in[4];
    const float* bq = (const float*)d_in[5];
    const float* Wk = (const float*)d_in[6];
    const float* bk = (const float*)d_in[7];
    const float* Wv = (const float*)d_in[8];
    const float* bv = (const float*)d_in[9];
    const float* Wo = (const float*)d_in[10];
    const float* bo = (const float*)d_in[11];
    const float* Wg = (const float*)d_in[12];
    const float* bg = (const float*)d_in[13];
    float* out = (float*)d_out;

    void *qh, *kh, *vh, *wqh, *wkh, *wvh, *woh;
    cudaGetSymbolAddress(&qh,  g_qh);
    cudaGetSymbolAddress(&kh,  g_kh);
    cudaGetSymbolAddress(&vh,  g_vh);
    cudaGetSymbolAddress(&wqh, g_Wqh);
    cudaGetSymbolAddress(&wkh, g_Wkh);
    cudaGetSymbolAddress(&wvh, g_Wvh);
    cudaGetSymbolAddress(&woh, g_Woh);

    cudaFuncSetAttribute(flash_mma_kernel,
                         cudaFuncAttributeMaxDynamicSharedMemorySize, FL_BYTES);
    cudaFuncSetAttribute(gemm_qkv_h_kernel,
                         cudaFuncAttributeMaxDynamicSharedMemorySize, G_BYTES);
    cudaFuncSetAttribute(gemm_out_kernel,
                         cudaFuncAttributeMaxDynamicSharedMemorySize, G_BYTES);

    // gate path (fp32, independent)
    mean_kernel<<<dim3(D / 256, B), 256>>>(query, memory);
    gate_vals_kernel<<<dim3(D / 256, B), 256>>>(Wg, bg);
    gate_reduce_kernel<<<1, 1024>>>();

    // convert inputs + weights to half
    const int nBig = BT * D;
    const int nW   = D * D;
    cvt_kernel<<<nBig / (256 * 8), 256>>>(query, (__half*)qh, nBig);
    cvt_kernel<<<nBig / (256 * 8), 256>>>(key,   (__half*)kh, nBig);
    cvt_kernel<<<nBig / (256 * 8), 256>>>(value, (__half*)vh, nBig);
    cvt_kernel<<<nW / (256 * 8), 256>>>(Wq, (__half*)wqh, nW);
    cvt_kernel<<<nW / (256 * 8), 256>>>(Wk, (__half*)wkh, nW);
    cvt_kernel<<<nW / (256 * 8), 256>>>(Wv, (__half*)wvh, nW);
    cvt_kernel<<<nW / (256 * 8), 256>>>(Wo, (__half*)woh, nW);

    // fused QKV projections
    gemm_qkv_h_kernel<<<dim3(D / 128, BT / 128, 3), 128, G_BYTES>>>(bq, bk, bv);

    // attention (128-key tiles, register softmax)
    flash_mma_kernel<<<dim3(T / 128, H, B), 256, FL_BYTES>>>(nullptr);

    // output projection -> d_out (fp32 out)
    gemm_out_kernel<<<dim3(D / 128, BT / 128), 128, G_BYTES>>>(bo, out);
}